// round 14
// baseline (speedup 1.0000x reference)
#include <cuda_runtime.h>
#include <cuda_fp16.h>
#include <cstdint>

#define N_NODES 50000
#define N_EDGES 800000
#define NODE_C  128
#define EDGE_C  64

// ---------------------------------------------------------------------------
// Device scratch (no cudaMalloc allowed)
// ---------------------------------------------------------------------------
__device__ float g_aggr[(size_t)N_NODES * EDGE_C];
__device__ __align__(16) float g_P[(size_t)N_NODES * 256];   // [n][0:128]=xn@eW1[0:128], [128:256]=xn@eW1[128:256]
__device__ __align__(16) __half g_xn_h[(size_t)N_NODES * NODE_C];
__device__ __align__(16) __half g_eW1t[128 * 320];
__device__ __align__(16) __half g_eW2t[64 * 128];
__device__ __align__(16) __half g_nW1t[128 * 192];
__device__ __align__(16) __half g_nW2t[128 * 128];

// ---------------------------------------------------------------------------
// Helpers
// ---------------------------------------------------------------------------
__device__ __forceinline__ uint32_t smem_u32(const void* p) {
    uint32_t a;
    asm("{ .reg .u64 t; cvta.to.shared.u64 t, %1; cvt.u32.u64 %0, t; }"
        : "=r"(a) : "l"(p));
    return a;
}

// Panels: [rows][64] fp16, 128-byte rows, XOR-swizzled 16B blocks.
__device__ __forceinline__ uint32_t panel_off(uint32_t r, uint32_t k) {
    return r * 128u + ((((k >> 3) ^ (r & 7u)) << 4) | ((k & 7u) << 1));
}

// fp32 stage: [64 rows][128 cols], 512B rows, 16B-block swizzle
__device__ __forceinline__ uint32_t stage_off(uint32_t row, uint32_t c4) {
    return row * 512u + (((c4 ^ (row & 7u)) & 31u) << 4);
}

__device__ __forceinline__ void ldsm_x4(uint32_t* d, uint32_t a) {
    asm volatile("ldmatrix.sync.aligned.m8n8.x4.shared.b16 {%0,%1,%2,%3}, [%4];"
                 : "=r"(d[0]), "=r"(d[1]), "=r"(d[2]), "=r"(d[3]) : "r"(a));
}

#define MMA16816(c, a, b) \
    asm volatile("mma.sync.aligned.m16n8k16.row.col.f32.f16.f16.f32 " \
        "{%0,%1,%2,%3},{%4,%5,%6,%7},{%8,%9},{%0,%1,%2,%3};" \
        : "+f"((c)[0]), "+f"((c)[1]), "+f"((c)[2]), "+f"((c)[3]) \
        : "r"((a)[0]), "r"((a)[1]), "r"((a)[2]), "r"((a)[3]), \
          "r"((b)[0]), "r"((b)[1]))

__device__ __forceinline__ void cp16(uint32_t dst, const void* src) {
    asm volatile("cp.async.cg.shared.global [%0], [%1], 16;"
                 :: "r"(dst), "l"(src) : "memory");
}
#define CP_COMMIT() asm volatile("cp.async.commit_group;" ::: "memory")
#define CP_WAIT(n)  asm volatile("cp.async.wait_group %0;" :: "n"(n) : "memory")

__device__ __forceinline__ uint32_t f16x2(float lo, float hi) {
    uint32_t r;
    asm("cvt.rn.f16x2.f32 %0, %1, %2;" : "=r"(r) : "f"(hi), "f"(lo));
    return r;
}
__device__ __forceinline__ float silu_f(float x) {
    return x / (1.0f + __expf(-x));
}
__device__ __forceinline__ uint4 pack8(float4 v0, float4 v1) {
    uint4 r;
    r.x = f16x2(v0.x, v0.y);
    r.y = f16x2(v0.z, v0.w);
    r.z = f16x2(v1.x, v1.y);
    r.w = f16x2(v1.z, v1.w);
    return r;
}

// ---------------------------------------------------------------------------
// Fused prep (R13 verbatim)
// ---------------------------------------------------------------------------
__global__ void prep_kernel(const float* __restrict__ xn,
                            const float* __restrict__ eW1,
                            const float* __restrict__ eW2,
                            const float* __restrict__ nW1,
                            const float* __restrict__ nW2) {
    int b = blockIdx.x;
    if (b < 3125) {
        size_t i = (size_t)b * 256 + threadIdx.x;
        if (i < (size_t)N_NODES * EDGE_C / 4)
            reinterpret_cast<float4*>(g_aggr)[i] = make_float4(0.f, 0.f, 0.f, 0.f);
    } else if (b < 9375) {
        size_t i = (size_t)(b - 3125) * 256 + threadIdx.x;
        if (i < (size_t)N_NODES * NODE_C / 4) {
            float4 v = reinterpret_cast<const float4*>(xn)[i];
            uint2 h;
            h.x = f16x2(v.x, v.y);
            h.y = f16x2(v.z, v.w);
            reinterpret_cast<uint2*>(g_xn_h)[i] = h;
        }
    } else {
        int i = (b - 9375) * 256 + threadIdx.x;
        if (i < 128 * 320) {
            int n = i / 320, k = i % 320;
            g_eW1t[i] = __float2half_rn(eW1[(size_t)k * 128 + n]);
        }
        if (i < 64 * 128) {
            int n = i / 128, k = i % 128;
            g_eW2t[i] = __float2half_rn(eW2[(size_t)k * 64 + n]);
        }
        if (i < 128 * 192) {
            int n = i / 192, k = i % 192;
            g_nW1t[i] = __float2half_rn(nW1[(size_t)k * 128 + n]);
        }
        if (i < 128 * 128) {
            int n = i / 128, k = i % 128;
            g_nW2t[i] = __float2half_rn(nW2[(size_t)k * 128 + n]);
        }
    }
}

// ---------------------------------------------------------------------------
// Precompute P: [50k,128] @ [128,256] -> fp32.
//   P[n][o*128+j] = sum_k xn_h[n][k] * eW1t[j][o*128+k]   (o = 0,1)
// 128 nodes/CTA, 256 threads, SMEM 96KB:
//   A panels (xn_h): p0@0, p1@16K        [128 r][64 k] each
//   B panels (eW1t k-chunks 0..3): 32K + kc*16K
// ---------------------------------------------------------------------------
#define PREP_P_SMEM 98304

__global__ __launch_bounds__(256, 2)
void precompute_P_kernel() {
    extern __shared__ __align__(1024) char dsm[];
    const int tid  = threadIdx.x;
    const int wid  = tid >> 5;
    const int lane = tid & 31;
    const int mw   = wid & 3;
    const int nw   = wid >> 2;
    const int m0   = blockIdx.x * 128;

    const uint32_t sb = smem_u32(dsm);
    const uint32_t la_r  = lane & 15;
    const uint32_t la_kb = (lane >> 4) << 3;
    const uint32_t lb_r  = (lane & 7) | ((lane >> 4) << 3);
    const uint32_t lb_kb = ((lane >> 3) & 1) << 3;

    // Load A (zero invalid rows first)
    {
        const int r = tid >> 1;
        const int half = tid & 1;
        const size_t node = (size_t)m0 + r;
        if (node < N_NODES) {
            const __half* a = g_xn_h + node * NODE_C + half * 64;
#pragma unroll
            for (int j = 0; j < 8; j++)
                cp16(sb + (uint32_t)(half * 16384) + panel_off((uint32_t)r, (uint32_t)(j * 8)), a + j * 8);
        } else {
            uint4 z = {0, 0, 0, 0};
#pragma unroll
            for (int j = 0; j < 8; j++)
                *(uint4*)(dsm + half * 16384 + panel_off((uint32_t)r, (uint32_t)(j * 8))) = z;
        }
    }
    // Load B (eW1t k 0..255 in 4 chunks)
    {
        const int n = tid >> 1;
        const int hb = tid & 1;
#pragma unroll
        for (int kc2 = 0; kc2 < 2; kc2++) {
            int kc = hb * 2 + kc2;
            const __half* s = g_eW1t + (size_t)n * 320 + kc * 64;
#pragma unroll
            for (int j = 0; j < 8; j++)
                cp16(sb + 32768u + (uint32_t)(kc * 16384) + panel_off((uint32_t)n, (uint32_t)(j * 8)), s + j * 8);
        }
    }
    CP_COMMIT();
    CP_WAIT(0);
    __syncthreads();

#pragma unroll 1
    for (int o = 0; o < 2; o++) {
        float c[2][8][4];
#pragma unroll
        for (int a = 0; a < 2; a++)
#pragma unroll
            for (int b = 0; b < 8; b++)
#pragma unroll
                for (int d = 0; d < 4; d++) c[a][b][d] = 0.f;

#pragma unroll
        for (int p = 0; p < 2; p++) {
            const uint32_t Ap = sb + (uint32_t)p * 16384u;
            const uint32_t Bp = sb + 32768u + (uint32_t)(o * 2 + p) * 16384u;
#pragma unroll
            for (int ks = 0; ks < 4; ks++) {
                const uint32_t kb = ks * 16;
                uint32_t a4[2][4];
#pragma unroll
                for (int mf = 0; mf < 2; mf++) {
                    uint32_t r = (uint32_t)(mw * 32 + mf * 16) + la_r;
                    ldsm_x4(a4[mf], Ap + panel_off(r, kb + la_kb));
                }
#pragma unroll
                for (int np = 0; np < 4; np++) {
                    uint32_t n = (uint32_t)(nw * 64 + np * 16) + lb_r;
                    uint32_t b4[4];
                    ldsm_x4(b4, Bp + panel_off(n, kb + lb_kb));
#pragma unroll
                    for (int mf = 0; mf < 2; mf++) {
                        MMA16816(c[mf][np * 2],     a4[mf], b4);
                        MMA16816(c[mf][np * 2 + 1], a4[mf], b4 + 2);
                    }
                }
            }
        }
        // store P fragments
        const int l4 = lane >> 2;
        const int l2 = (lane & 3) * 2;
#pragma unroll
        for (int mf = 0; mf < 2; mf++) {
#pragma unroll
            for (int half = 0; half < 2; half++) {
                size_t node = (size_t)m0 + mw * 32 + mf * 16 + l4 + half * 8;
                if (node < N_NODES) {
                    float* prow = g_P + node * 256 + o * 128;
#pragma unroll
                    for (int nf = 0; nf < 8; nf++) {
                        int col = nw * 64 + nf * 8 + l2;
                        float2 v = {c[mf][nf][half * 2], c[mf][nf][half * 2 + 1]};
                        *reinterpret_cast<float2*>(prow + col) = v;
                    }
                }
            }
        }
    }
}

// ---------------------------------------------------------------------------
// Edge kernel: 64 edges / CTA, 256 threads, 2 CTAs/SM. SMEM 72KB:
//   A (xe fp16 [64][64])      @0      (8K)
//   B1 (eW1t k256..320 [128][64]) @8K (16K)
//   B2 (eW2t): p0@24K, p1@32K (8K each)
//   stage [64][128] fp32      @40K    (32K)
//   h panels (after pass2): p0@0, p1@8K
// GEMM1': xe @ eW1[256:320]  -> stage; pass2: + P[snd] + P[rcv] + bias, SiLU
// GEMM2: h @ eW2t -> out
// ---------------------------------------------------------------------------
#define EDGE_SMEM 73728
#define NODE_SMEM 73728

__global__ __launch_bounds__(256, 2)
void edge_mma_kernel(const float* __restrict__ xe,
                     const void*  __restrict__ eidx,
                     const float* __restrict__ eb1,
                     const float* __restrict__ eb2,
                     float* __restrict__ edges_out)
{
    extern __shared__ __align__(1024) char dsm[];
    __shared__ int s_snd[64], s_rcv[64];

    const int tid  = threadIdx.x;
    const int wid  = tid >> 5;
    const int lane = tid & 31;
    const int mw   = wid & 1;      // 2 M strips (32 rows)
    const int nw   = wid >> 1;     // 4 N strips (32 cols GEMM1' / 16 cols GEMM2)
    const int e0   = blockIdx.x * 64;

    const uint32_t sb = smem_u32(dsm);
    const uint32_t la_r  = lane & 15;
    const uint32_t la_kb = (lane >> 4) << 3;
    const uint32_t lb_r  = (lane & 7) | ((lane >> 4) << 3);
    const uint32_t lb_kb = ((lane >> 3) & 1) << 3;

    // edge indices
    {
        const unsigned* w = reinterpret_cast<const unsigned*>(eidx);
        const bool is64 = ((w[1] | w[3] | w[5] | w[7] | w[9] | w[11] | w[13] | w[15]) == 0u);
        if (tid < 64) {
            size_t e = (size_t)e0 + tid;
            if (is64) {
                const long long* p = reinterpret_cast<const long long*>(eidx);
                s_snd[tid] = (int)p[e];
                s_rcv[tid] = (int)p[(size_t)N_EDGES + e];
            } else {
                const int* p = reinterpret_cast<const int*>(eidx);
                s_snd[tid] = p[e];
                s_rcv[tid] = p[(size_t)N_EDGES + e];
            }
        }
    }

    // cp.async: B1 (eW1t k-offset 256) + B2 (eW2t)
    {
        const int n = tid >> 1;
        const int bq = tid & 1;
        const __half* s = g_eW1t + (size_t)n * 320 + 256 + bq * 32;
#pragma unroll
        for (int j = 0; j < 4; j++)
            cp16(sb + 8192u + panel_off((uint32_t)n, (uint32_t)(bq * 32 + j * 8)), s + j * 8);
        const int n2 = tid >> 2;
        const int q2 = tid & 3;
        const __half* s2 = g_eW2t + (size_t)n2 * 128;
#pragma unroll
        for (int j = 0; j < 4; j++) {
            int seg = q2 * 4 + j;
            uint32_t p = (uint32_t)(seg >> 3);
            cp16(sb + 24576u + p * 8192u + panel_off((uint32_t)n2, (uint32_t)((seg & 7) * 8)), s2 + seg * 8);
        }
        CP_COMMIT();
    }
    // xe -> fp16 panel (LDG + pack + STS)
    {
        const int row = tid >> 2;
        const int q   = tid & 3;
        const float4* rp = reinterpret_cast<const float4*>(xe + (size_t)(e0 + row) * EDGE_C) + q * 4;
        float4 v0 = rp[0], v1 = rp[1], v2 = rp[2], v3 = rp[3];
        *(uint4*)(dsm + panel_off((uint32_t)row, (uint32_t)(q * 16)))     = pack8(v0, v1);
        *(uint4*)(dsm + panel_off((uint32_t)row, (uint32_t)(q * 16 + 8))) = pack8(v2, v3);
    }
    CP_WAIT(0);
    __syncthreads();

    // ---------------- GEMM1': xe[64,64] @ B1^T -> [64,128] ----------------
    float c1[2][4][4];
#pragma unroll
    for (int a = 0; a < 2; a++)
#pragma unroll
        for (int b = 0; b < 4; b++)
#pragma unroll
            for (int d = 0; d < 4; d++) c1[a][b][d] = 0.f;

#pragma unroll
    for (int ks = 0; ks < 4; ks++) {
        const uint32_t kb = ks * 16;
        uint32_t a4[2][4];
#pragma unroll
        for (int mf = 0; mf < 2; mf++) {
            uint32_t r = (uint32_t)(mw * 32 + mf * 16) + la_r;
            ldsm_x4(a4[mf], sb + panel_off(r, kb + la_kb));
        }
#pragma unroll
        for (int np = 0; np < 2; np++) {
            uint32_t n = (uint32_t)(nw * 32 + np * 16) + lb_r;
            uint32_t b4[4];
            ldsm_x4(b4, sb + 8192u + panel_off(n, kb + lb_kb));
#pragma unroll
            for (int mf = 0; mf < 2; mf++) {
                MMA16816(c1[mf][np * 2],     a4[mf], b4);
                MMA16816(c1[mf][np * 2 + 1], a4[mf], b4 + 2);
            }
        }
    }

    // stage fragments (fp32) @40K
    {
        const int l4 = lane >> 2;
        const int l2 = (lane & 3) * 2;
#pragma unroll
        for (int mf = 0; mf < 2; mf++) {
#pragma unroll
            for (int half = 0; half < 2; half++) {
                uint32_t row = (uint32_t)(mw * 32 + mf * 16 + l4 + half * 8);
#pragma unroll
                for (int nf = 0; nf < 4; nf++) {
                    uint32_t col = (uint32_t)(nw * 32 + nf * 8 + l2);
                    float2 v = {c1[mf][nf][half * 2], c1[mf][nf][half * 2 + 1]};
                    *(float2*)(dsm + 40960u + stage_off(row, col >> 2) + (col & 3) * 4) = v;
                }
            }
        }
    }
    __syncthreads();

    // ---------------- pass2: + P[snd] + P[rcv] + bias -> SiLU -> h panels ----------------
    {
        const int row = tid >> 2;      // edge row 0..63
        const int q   = tid & 3;       // 32-col quarter
        const float* p1 = g_P + (size_t)s_snd[row] * 256 + q * 32;
        const float* p2 = g_P + (size_t)s_rcv[row] * 256 + 128 + q * 32;
        const float* bb = eb1 + q * 32;
        const uint32_t hpan = (uint32_t)(q >> 1) * 8192u;         // panel p = col>>6
        const uint32_t kbase = (uint32_t)((q & 1) * 32);
#pragma unroll
        for (int g = 0; g < 2; g++) {
            float4 v1[4], v2[4], vb[4], st[4];
#pragma unroll
            for (int j = 0; j < 4; j++) {
                int jj = g * 4 + j;
                v1[j] = *reinterpret_cast<const float4*>(p1 + jj * 4);
                v2[j] = *reinterpret_cast<const float4*>(p2 + jj * 4);
                vb[j] = *reinterpret_cast<const float4*>(bb + jj * 4);
                st[j] = *(float4*)(dsm + 40960u + stage_off((uint32_t)row, (uint32_t)(q * 8 + jj)));
            }
#pragma unroll
            for (int j = 0; j < 4; j++) {
                st[j].x = silu_f(st[j].x + v1[j].x + v2[j].x + vb[j].x);
                st[j].y = silu_f(st[j].y + v1[j].y + v2[j].y + vb[j].y);
                st[j].z = silu_f(st[j].z + v1[j].z + v2[j].z + vb[j].z);
                st[j].w = silu_f(st[j].w + v1[j].w + v2[j].w + vb[j].w);
            }
            // 16 values -> 2 uint4 panel stores (k = kbase + g*16 .. +15)
            *(uint4*)(dsm + hpan + panel_off((uint32_t)row, kbase + g * 16))     = pack8(st[0], st[1]);
            *(uint4*)(dsm + hpan + panel_off((uint32_t)row, kbase + g * 16 + 8)) = pack8(st[2], st[3]);
        }
    }
    __syncthreads();

    // ---------------- GEMM2: h[64,128] @ eW2t^T -> [64,64] ----------------
    float c2[2][2][4];
#pragma unroll
    for (int a = 0; a < 2; a++)
#pragma unroll
        for (int b = 0; b < 2; b++)
#pragma unroll
            for (int d = 0; d < 4; d++) c2[a][b][d] = 0.f;

#pragma unroll
    for (int p = 0; p < 2; p++) {
        const uint32_t Ap = sb + (uint32_t)p * 8192u;
        const uint32_t Bp = sb + 24576u + (uint32_t)p * 8192u;
#pragma unroll
        for (int ks = 0; ks < 4; ks++) {
            const uint32_t kb = ks * 16;
            uint32_t a4[2][4];
#pragma unroll
            for (int mf = 0; mf < 2; mf++) {
                uint32_t r = (uint32_t)(mw * 32 + mf * 16) + la_r;
                ldsm_x4(a4[mf], Ap + panel_off(r, kb + la_kb));
            }
            uint32_t n = (uint32_t)(nw * 16) + lb_r;
            uint32_t b4[4];
            ldsm_x4(b4, Bp + panel_off(n, kb + lb_kb));
#pragma unroll
            for (int mf = 0; mf < 2; mf++) {
                MMA16816(c2[mf][0], a4[mf], b4);
                MMA16816(c2[mf][1], a4[mf], b4 + 2);
            }
        }
    }

    // ---------------- Epilogue2: SiLU, store, scatter-add ----------------
    {
        const int l4 = lane >> 2;
        const int l2 = (lane & 3) * 2;
        float b0[2], b1[2];
#pragma unroll
        for (int nf = 0; nf < 2; nf++) {
            int col = nw * 16 + nf * 8 + l2;
            b0[nf] = __ldg(eb2 + col);
            b1[nf] = __ldg(eb2 + col + 1);
        }
#pragma unroll
        for (int mf = 0; mf < 2; mf++) {
#pragma unroll
            for (int half = 0; half < 2; half++) {
                int m = mw * 32 + mf * 16 + l4 + half * 8;
                int rcv = s_rcv[m];
                float* orow = edges_out + (size_t)(e0 + m) * EDGE_C;
                float* arow = g_aggr + (size_t)rcv * EDGE_C;
#pragma unroll
                for (int nf = 0; nf < 2; nf++) {
                    int col = nw * 16 + nf * 8 + l2;
                    float o0 = silu_f(c2[mf][nf][half * 2]     + b0[nf]);
                    float o1 = silu_f(c2[mf][nf][half * 2 + 1] + b1[nf]);
                    float2 ov = {o0, o1};
                    *reinterpret_cast<float2*>(orow + col) = ov;
                    atomicAdd(arow + col,     o0);
                    atomicAdd(arow + col + 1, o1);
                }
            }
        }
    }
}

// ---------------------------------------------------------------------------
// Node kernel: 64 nodes / CTA, 256 threads, 2 CTAs/SM (R13 verbatim)
// ---------------------------------------------------------------------------
__global__ __launch_bounds__(256, 2)
void node_mma_kernel(const float* __restrict__ xn,
                     const float* __restrict__ nb1,
                     const float* __restrict__ nb2,
                     float* __restrict__ nodes_out)
{
    extern __shared__ __align__(1024) char dsm[];

    const int tid  = threadIdx.x;
    const int wid  = tid >> 5;
    const int lane = tid & 31;
    const int mw   = wid & 1;
    const int nw   = wid >> 1;
    const int m0   = blockIdx.x * 64;

    const uint32_t sb = smem_u32(dsm);
    const uint32_t la_r  = lane & 15;
    const uint32_t la_kb = (lane >> 4) << 3;
    const uint32_t lb_r  = (lane & 7) | ((lane >> 4) << 3);
    const uint32_t lb_kb = ((lane >> 3) & 1) << 3;

    const int gm = tid >> 2;
    const int gq = tid & 3;
    const int bn = tid >> 1;
    const int bq = tid & 1;
    const size_t grow = (size_t)m0 + gm;
    const bool gvalid = grow < N_NODES;

    {
        const __half* s = g_nW1t + (size_t)bn * 192 + bq * 32;
#pragma unroll
        for (int j = 0; j < 4; j++) {
            uint32_t off = panel_off((uint32_t)bn, (uint32_t)(bq * 32 + j * 8));
            cp16(sb + 8192u + off, s + j * 8);
        }
        CP_COMMIT();
    }
    float4 av[4];
    {
        const float4* rp = reinterpret_cast<const float4*>(xn + grow * NODE_C) + gq * 4;
#pragma unroll
        for (int i = 0; i < 4; i++)
            av[i] = gvalid ? rp[i] : make_float4(0.f, 0.f, 0.f, 0.f);
    }

    float c[2][4][4];
#pragma unroll
    for (int a = 0; a < 2; a++)
#pragma unroll
        for (int b = 0; b < 4; b++)
#pragma unroll
            for (int d = 0; d < 4; d++) c[a][b][d] = 0.f;

#pragma unroll 1
    for (int ch = 0; ch < 3; ch++) {
        __syncthreads();
#pragma unroll
        for (int i = 0; i < 2; i++) {
            uint32_t off = panel_off((uint32_t)gm, (uint32_t)(gq * 16 + i * 8));
            *(uint4*)(dsm + off) = pack8(av[2 * i], av[2 * i + 1]);
        }
        if (ch < 2) {
            const int nc = ch + 1;
            uint32_t dst = 8192u + (uint32_t)((nc & 1) * 16384);
            const __half* s = g_nW1t + (size_t)bn * 192 + nc * 64 + bq * 32;
#pragma unroll
            for (int j = 0; j < 4; j++) {
                uint32_t off = panel_off((uint32_t)bn, (uint32_t)(bq * 32 + j * 8));
                cp16(sb + dst + off, s + j * 8);
            }
            CP_COMMIT();
            const float* rowp = (nc < 2) ? xn + grow * NODE_C + nc * 64
                                         : g_aggr + grow * EDGE_C;
            const float4* rp = reinterpret_cast<const float4*>(rowp) + gq * 4;
#pragma unroll
            for (int i = 0; i < 4; i++)
                av[i] = gvalid ? rp[i] : make_float4(0.f, 0.f, 0.f, 0.f);
        } else {
            const __half* s = g_nW2t + (size_t)bn * 128;
#pragma unroll
            for (int j = 0; j < 8; j++) {
                int seg = bq * 8 + j;
                uint32_t p = (uint32_t)(seg >> 3);
                uint32_t off = p * 16384u + panel_off((uint32_t)bn, (uint32_t)((seg & 7) * 8));
                cp16(sb + 40960u + off, s + seg * 8);
            }
            CP_COMMIT();
        }
        CP_WAIT(1);
        __syncthreads();

        const uint32_t Bp = sb + 8192u + (uint32_t)((ch & 1) * 16384);
#pragma unroll
        for (int ks = 0; ks < 4; ks++) {
            const uint32_t kb = ks * 16;
            uint32_t a4[2][4];
#pragma unroll
            for (int mf = 0; mf < 2; mf++) {
                uint32_t r = (uint32_t)(mw * 32 + mf * 16) + la_r;
                ldsm_x4(a4[mf], sb + panel_off(r, kb + la_kb));
            }
#pragma unroll
            for (int np = 0; np < 2; np++) {
                uint32_t n = (uint32_t)(nw * 32 + np * 16) + lb_r;
                uint32_t b4[4];
                ldsm_x4(b4, Bp + panel_off(n, kb + lb_kb));
#pragma unroll
                for (int mf = 0; mf < 2; mf++) {
                    MMA16816(c[mf][np * 2],     a4[mf], b4);
                    MMA16816(c[mf][np * 2 + 1], a4[mf], b4 + 2);
                }
            }
        }
    }
    __syncthreads();

    {
        const int l4 = lane >> 2;
        const int l2 = (lane & 3) * 2;
        const uint32_t hb = (uint32_t)(nw >> 1) * 8192u;
#pragma unroll
        for (int nf = 0; nf < 4; nf++) {
            int col = nw * 32 + nf * 8 + l2;
            float b0 = __ldg(nb1 + col), b1 = __ldg(nb1 + col + 1);
            uint32_t kk = (uint32_t)((nw & 1) * 32 + nf * 8 + l2);
#pragma unroll
            for (int mf = 0; mf < 2; mf++) {
                uint32_t m = (uint32_t)(mw * 32 + mf * 16 + l4);
                float x0 = silu_f(c[mf][nf][0] + b0);
                float x1 = silu_f(c[mf][nf][1] + b1);
                float x2 = silu_f(c[mf][nf][2] + b0);
                float x3 = silu_f(c[mf][nf][3] + b1);
                *(uint32_t*)(dsm + hb + panel_off(m, kk))     = f16x2(x0, x1);
                *(uint32_t*)(dsm + hb + panel_off(m + 8, kk)) = f16x2(x2, x3);
            }
        }
    }
    CP_WAIT(0);
    __syncthreads();

    float c2[2][4][4];
#pragma unroll
    for (int a = 0; a < 2; a++)
#pragma unroll
        for (int b = 0; b < 4; b++)
#pragma unroll
            for (int d = 0; d < 4; d++) c2[a][b][d] = 0.f;

#pragma unroll
    for (int p = 0; p < 2; p++) {
        const uint32_t Ap = sb + (uint32_t)p * 8192u;
        const uint32_t Bp = sb + 40960u + (uint32_t)p * 16384u;
#pragma unroll
        for (int ks = 0; ks < 4; ks++) {
            const uint32_t kb = ks * 16;
            uint32_t a4[2][4];
#pragma unroll
            for (int mf = 0; mf < 2; mf++) {
                uint32_t r = (uint32_t)(mw * 32 + mf * 16) + la_r;
                ldsm_x4(a4[mf], Ap + panel_off(r, kb + la_kb));
            }
#pragma unroll
            for (int np = 0; np < 2; np++) {
                uint32_t n = (uint32_t)(nw * 32 + np * 16) + lb_r;
                uint32_t b4[4];
                ldsm_x4(b4, Bp + panel_off(n, kb + lb_kb));
#pragma unroll
                for (int mf = 0; mf < 2; mf++) {
                    MMA16816(c2[mf][np * 2],     a4[mf], b4);
                    MMA16816(c2[mf][np * 2 + 1], a4[mf], b4 + 2);
                }
            }
        }
    }

    {
        const int l4 = lane >> 2;
        const int l2 = (lane & 3) * 2;
        float b0[4], b1[4];
#pragma unroll
        for (int nf = 0; nf < 4; nf++) {
            int col = nw * 32 + nf * 8 + l2;
            b0[nf] = __ldg(nb2 + col);
            b1[nf] = __ldg(nb2 + col + 1);
        }
#pragma unroll
        for (int mf = 0; mf < 2; mf++) {
#pragma unroll
            for (int half = 0; half < 2; half++) {
                size_t row = (size_t)m0 + mw * 32 + mf * 16 + l4 + half * 8;
                if (row < N_NODES) {
                    float* orow = nodes_out + row * NODE_C;
#pragma unroll
                    for (int nf = 0; nf < 4; nf++) {
                        int col = nw * 32 + nf * 8 + l2;
                        float2 ov;
                        ov.x = c2[mf][nf][half * 2]     + b0[nf];
                        ov.y = c2[mf][nf][half * 2 + 1] + b1[nf];
                        *reinterpret_cast<float2*>(orow + col) = ov;
                    }
                }
            }
        }
    }
}

// ---------------------------------------------------------------------------
extern "C" void kernel_launch(void* const* d_in, const int* in_sizes, int n_in,
                              void* d_out, int out_size)
{
    const float* xn   = (const float*)d_in[0];
    const float* xe   = (const float*)d_in[1];
    const void*  eidx =               d_in[2];
    const float* eW1  = (const float*)d_in[3];
    const float* eb1  = (const float*)d_in[4];
    const float* eW2  = (const float*)d_in[5];
    const float* eb2  = (const float*)d_in[6];
    const float* nW1  = (const float*)d_in[7];
    const float* nb1  = (const float*)d_in[8];
    const float* nW2  = (const float*)d_in[9];
    const float* nb2  = (const float*)d_in[10];

    float* nodes_out = (float*)d_out;
    float* edges_out = (float*)d_out + (size_t)N_NODES * NODE_C;

    cudaFuncSetAttribute(precompute_P_kernel, cudaFuncAttributeMaxDynamicSharedMemorySize, PREP_P_SMEM);
    cudaFuncSetAttribute(edge_mma_kernel, cudaFuncAttributeMaxDynamicSharedMemorySize, EDGE_SMEM);
    cudaFuncSetAttribute(node_mma_kernel, cudaFuncAttributeMaxDynamicSharedMemorySize, NODE_SMEM);

    prep_kernel<<<9535, 256>>>(xn, eW1, eW2, nW1, nW2);
    precompute_P_kernel<<<(N_NODES + 127) / 128, 256, PREP_P_SMEM>>>();
    edge_mma_kernel<<<N_EDGES / 64, 256, EDGE_SMEM>>>(xe, eidx, eb1, eb2, edges_out);
    node_mma_kernel<<<(N_NODES + 63) / 64, 256, NODE_SMEM>>>(xn, nb1, nb2, nodes_out);
}

// round 15
// speedup vs baseline: 1.3275x; 1.3275x over previous
#include <cuda_runtime.h>
#include <cuda_fp16.h>
#include <cstdint>

#define N_NODES 50000
#define N_EDGES 800000
#define NODE_C  128
#define EDGE_C  64

// ---------------------------------------------------------------------------
// Device scratch (no cudaMalloc allowed)
// ---------------------------------------------------------------------------
__device__ float g_aggr[(size_t)N_NODES * EDGE_C];
// P (fp16): [n][0:128]=xn@eW1[0:128], [n][128:256]=xn@eW1[128:256]
__device__ __align__(16) __half g_P_h[(size_t)N_NODES * 256];
__device__ __align__(16) __half g_xn_h[(size_t)N_NODES * NODE_C];
__device__ __align__(16) __half g_eW1t[128 * 320];
__device__ __align__(16) __half g_eW2t[64 * 128];
__device__ __align__(16) __half g_nW1t[128 * 192];
__device__ __align__(16) __half g_nW2t[128 * 128];

// ---------------------------------------------------------------------------
// Helpers
// ---------------------------------------------------------------------------
__device__ __forceinline__ uint32_t smem_u32(const void* p) {
    uint32_t a;
    asm("{ .reg .u64 t; cvta.to.shared.u64 t, %1; cvt.u32.u64 %0, t; }"
        : "=r"(a) : "l"(p));
    return a;
}

// Panels: [rows][64] fp16, 128-byte rows, XOR-swizzled 16B blocks.
__device__ __forceinline__ uint32_t panel_off(uint32_t r, uint32_t k) {
    return r * 128u + ((((k >> 3) ^ (r & 7u)) << 4) | ((k & 7u) << 1));
}

__device__ __forceinline__ void ldsm_x4(uint32_t* d, uint32_t a) {
    asm volatile("ldmatrix.sync.aligned.m8n8.x4.shared.b16 {%0,%1,%2,%3}, [%4];"
                 : "=r"(d[0]), "=r"(d[1]), "=r"(d[2]), "=r"(d[3]) : "r"(a));
}

#define MMA16816(c, a, b) \
    asm volatile("mma.sync.aligned.m16n8k16.row.col.f32.f16.f16.f32 " \
        "{%0,%1,%2,%3},{%4,%5,%6,%7},{%8,%9},{%0,%1,%2,%3};" \
        : "+f"((c)[0]), "+f"((c)[1]), "+f"((c)[2]), "+f"((c)[3]) \
        : "r"((a)[0]), "r"((a)[1]), "r"((a)[2]), "r"((a)[3]), \
          "r"((b)[0]), "r"((b)[1]))

__device__ __forceinline__ void cp16(uint32_t dst, const void* src) {
    asm volatile("cp.async.cg.shared.global [%0], [%1], 16;"
                 :: "r"(dst), "l"(src) : "memory");
}
#define CP_COMMIT() asm volatile("cp.async.commit_group;" ::: "memory")
#define CP_WAIT(n)  asm volatile("cp.async.wait_group %0;" :: "n"(n) : "memory")

__device__ __forceinline__ uint32_t f16x2(float lo, float hi) {
    uint32_t r;
    asm("cvt.rn.f16x2.f32 %0, %1, %2;" : "=r"(r) : "f"(hi), "f"(lo));
    return r;
}
__device__ __forceinline__ float silu_f(float x) {
    return x / (1.0f + __expf(-x));
}
__device__ __forceinline__ uint4 pack8(float4 v0, float4 v1) {
    uint4 r;
    r.x = f16x2(v0.x, v0.y);
    r.y = f16x2(v0.z, v0.w);
    r.z = f16x2(v1.x, v1.y);
    r.w = f16x2(v1.z, v1.w);
    return r;
}

// ---------------------------------------------------------------------------
// Fused prep (R13 verbatim)
// ---------------------------------------------------------------------------
__global__ void prep_kernel(const float* __restrict__ xn,
                            const float* __restrict__ eW1,
                            const float* __restrict__ eW2,
                            const float* __restrict__ nW1,
                            const float* __restrict__ nW2) {
    int b = blockIdx.x;
    if (b < 3125) {
        size_t i = (size_t)b * 256 + threadIdx.x;
        if (i < (size_t)N_NODES * EDGE_C / 4)
            reinterpret_cast<float4*>(g_aggr)[i] = make_float4(0.f, 0.f, 0.f, 0.f);
    } else if (b < 9375) {
        size_t i = (size_t)(b - 3125) * 256 + threadIdx.x;
        if (i < (size_t)N_NODES * NODE_C / 4) {
            float4 v = reinterpret_cast<const float4*>(xn)[i];
            uint2 h;
            h.x = f16x2(v.x, v.y);
            h.y = f16x2(v.z, v.w);
            reinterpret_cast<uint2*>(g_xn_h)[i] = h;
        }
    } else {
        int i = (b - 9375) * 256 + threadIdx.x;
        if (i < 128 * 320) {
            int n = i / 320, k = i % 320;
            g_eW1t[i] = __float2half_rn(eW1[(size_t)k * 128 + n]);
        }
        if (i < 64 * 128) {
            int n = i / 128, k = i % 128;
            g_eW2t[i] = __float2half_rn(eW2[(size_t)k * 64 + n]);
        }
        if (i < 128 * 192) {
            int n = i / 192, k = i % 192;
            g_nW1t[i] = __float2half_rn(nW1[(size_t)k * 128 + n]);
        }
        if (i < 128 * 128) {
            int n = i / 128, k = i % 128;
            g_nW2t[i] = __float2half_rn(nW2[(size_t)k * 128 + n]);
        }
    }
}

// ---------------------------------------------------------------------------
// Precompute P (fp16 output): [50k,128] @ [128,256]
// 128 nodes/CTA, 256 threads, SMEM 96KB.
// ---------------------------------------------------------------------------
#define PREP_P_SMEM 98304

__global__ __launch_bounds__(256, 2)
void precompute_P_kernel() {
    extern __shared__ __align__(1024) char dsm[];
    const int tid  = threadIdx.x;
    const int wid  = tid >> 5;
    const int lane = tid & 31;
    const int mw   = wid & 3;
    const int nw   = wid >> 2;
    const int m0   = blockIdx.x * 128;

    const uint32_t sb = smem_u32(dsm);
    const uint32_t la_r  = lane & 15;
    const uint32_t la_kb = (lane >> 4) << 3;
    const uint32_t lb_r  = (lane & 7) | ((lane >> 4) << 3);
    const uint32_t lb_kb = ((lane >> 3) & 1) << 3;

    // Load A (zero invalid rows)
    {
        const int r = tid >> 1;
        const int half = tid & 1;
        const size_t node = (size_t)m0 + r;
        if (node < N_NODES) {
            const __half* a = g_xn_h + node * NODE_C + half * 64;
#pragma unroll
            for (int j = 0; j < 8; j++)
                cp16(sb + (uint32_t)(half * 16384) + panel_off((uint32_t)r, (uint32_t)(j * 8)), a + j * 8);
        } else {
            uint4 z = {0, 0, 0, 0};
#pragma unroll
            for (int j = 0; j < 8; j++)
                *(uint4*)(dsm + half * 16384 + panel_off((uint32_t)r, (uint32_t)(j * 8))) = z;
        }
    }
    // Load B (eW1t k 0..255 in 4 chunks)
    {
        const int n = tid >> 1;
        const int hb = tid & 1;
#pragma unroll
        for (int kc2 = 0; kc2 < 2; kc2++) {
            int kc = hb * 2 + kc2;
            const __half* s = g_eW1t + (size_t)n * 320 + kc * 64;
#pragma unroll
            for (int j = 0; j < 8; j++)
                cp16(sb + 32768u + (uint32_t)(kc * 16384) + panel_off((uint32_t)n, (uint32_t)(j * 8)), s + j * 8);
        }
    }
    CP_COMMIT();
    CP_WAIT(0);
    __syncthreads();

#pragma unroll 1
    for (int o = 0; o < 2; o++) {
        float c[2][8][4];
#pragma unroll
        for (int a = 0; a < 2; a++)
#pragma unroll
            for (int b = 0; b < 8; b++)
#pragma unroll
                for (int d = 0; d < 4; d++) c[a][b][d] = 0.f;

#pragma unroll
        for (int p = 0; p < 2; p++) {
            const uint32_t Ap = sb + (uint32_t)p * 16384u;
            const uint32_t Bp = sb + 32768u + (uint32_t)(o * 2 + p) * 16384u;
#pragma unroll
            for (int ks = 0; ks < 4; ks++) {
                const uint32_t kb = ks * 16;
                uint32_t a4[2][4];
#pragma unroll
                for (int mf = 0; mf < 2; mf++) {
                    uint32_t r = (uint32_t)(mw * 32 + mf * 16) + la_r;
                    ldsm_x4(a4[mf], Ap + panel_off(r, kb + la_kb));
                }
#pragma unroll
                for (int np = 0; np < 4; np++) {
                    uint32_t n = (uint32_t)(nw * 64 + np * 16) + lb_r;
                    uint32_t b4[4];
                    ldsm_x4(b4, Bp + panel_off(n, kb + lb_kb));
#pragma unroll
                    for (int mf = 0; mf < 2; mf++) {
                        MMA16816(c[mf][np * 2],     a4[mf], b4);
                        MMA16816(c[mf][np * 2 + 1], a4[mf], b4 + 2);
                    }
                }
            }
        }
        const int l4 = lane >> 2;
        const int l2 = (lane & 3) * 2;
#pragma unroll
        for (int mf = 0; mf < 2; mf++) {
#pragma unroll
            for (int half = 0; half < 2; half++) {
                size_t node = (size_t)m0 + mw * 32 + mf * 16 + l4 + half * 8;
                if (node < N_NODES) {
                    __half* prow = g_P_h + node * 256 + o * 128;
#pragma unroll
                    for (int nf = 0; nf < 8; nf++) {
                        int col = nw * 64 + nf * 8 + l2;
                        *(uint32_t*)(prow + col) = f16x2(c[mf][nf][half * 2], c[mf][nf][half * 2 + 1]);
                    }
                }
            }
        }
    }
}

// ---------------------------------------------------------------------------
// Edge kernel: 64 edges / CTA, 256 threads, 2 CTAs/SM. SMEM 75776B:
//   A (xe fp16 [64][64])           @0      (8K)
//   B1 (eW1t k256..320 [128][64])  @8K     (16K)
//   B2 (eW2t): p0@24K, p1@32K      (8K each)
//   Ps [64 rows][128 h, 272B row stride] @40960   (17408B)
//   Pr                              @58368  (17408B)
//   h panels (after GEMM1'): p0@0, p1@8K
// ---------------------------------------------------------------------------
#define EDGE_SMEM 75776
#define NODE_SMEM 73728

__global__ __launch_bounds__(256, 2)
void edge_mma_kernel(const float* __restrict__ xe,
                     const void*  __restrict__ eidx,
                     const float* __restrict__ eb1,
                     const float* __restrict__ eb2,
                     float* __restrict__ edges_out)
{
    extern __shared__ __align__(1024) char dsm[];
    __shared__ int s_snd[64], s_rcv[64];

    const int tid  = threadIdx.x;
    const int wid  = tid >> 5;
    const int lane = tid & 31;
    const int mw   = wid & 1;      // 2 M strips (32 rows)
    const int nw   = wid >> 1;     // 4 N strips (32 cols GEMM1' / 16 cols GEMM2)
    const int e0   = blockIdx.x * 64;

    const uint32_t sb = smem_u32(dsm);
    const uint32_t la_r  = lane & 15;
    const uint32_t la_kb = (lane >> 4) << 3;
    const uint32_t lb_r  = (lane & 7) | ((lane >> 4) << 3);
    const uint32_t lb_kb = ((lane >> 3) & 1) << 3;

    // edge indices
    {
        const unsigned* w = reinterpret_cast<const unsigned*>(eidx);
        const bool is64 = ((w[1] | w[3] | w[5] | w[7] | w[9] | w[11] | w[13] | w[15]) == 0u);
        if (tid < 64) {
            size_t e = (size_t)e0 + tid;
            if (is64) {
                const long long* p = reinterpret_cast<const long long*>(eidx);
                s_snd[tid] = (int)p[e];
                s_rcv[tid] = (int)p[(size_t)N_EDGES + e];
            } else {
                const int* p = reinterpret_cast<const int*>(eidx);
                s_snd[tid] = p[e];
                s_rcv[tid] = p[(size_t)N_EDGES + e];
            }
        }
    }
    __syncthreads();

    // cp.async group: B1 + B2 + Ps + Pr  (P gather hidden under xe pack + GEMM1')
    {
        const int n = tid >> 1;
        const int bq = tid & 1;
        const __half* s = g_eW1t + (size_t)n * 320 + 256 + bq * 32;
#pragma unroll
        for (int j = 0; j < 4; j++)
            cp16(sb + 8192u + panel_off((uint32_t)n, (uint32_t)(bq * 32 + j * 8)), s + j * 8);

        const int n2 = tid >> 2;
        const int q2 = tid & 3;
        const __half* s2 = g_eW2t + (size_t)n2 * 128;
#pragma unroll
        for (int j = 0; j < 4; j++) {
            int seg = q2 * 4 + j;
            uint32_t p = (uint32_t)(seg >> 3);
            cp16(sb + 24576u + p * 8192u + panel_off((uint32_t)n2, (uint32_t)((seg & 7) * 8)), s2 + seg * 8);
        }

        const int prow = tid >> 2;     // 0..63
        const int pq   = tid & 3;      // 64B quarter
        const __half* ps = g_P_h + (size_t)s_snd[prow] * 256 + pq * 32;
        const __half* pr = g_P_h + (size_t)s_rcv[prow] * 256 + 128 + pq * 32;
        uint32_t pbase = (uint32_t)(prow * 272 + pq * 64);
#pragma unroll
        for (int j = 0; j < 4; j++) {
            cp16(sb + 40960u + pbase + j * 16, ps + j * 8);
            cp16(sb + 58368u + pbase + j * 16, pr + j * 8);
        }
        CP_COMMIT();
    }
    // xe -> fp16 panel @0
    {
        const int row = tid >> 2;
        const int q   = tid & 3;
        const float4* rp = reinterpret_cast<const float4*>(xe + (size_t)(e0 + row) * EDGE_C) + q * 4;
        float4 v0 = rp[0], v1 = rp[1], v2 = rp[2], v3 = rp[3];
        *(uint4*)(dsm + panel_off((uint32_t)row, (uint32_t)(q * 16)))     = pack8(v0, v1);
        *(uint4*)(dsm + panel_off((uint32_t)row, (uint32_t)(q * 16 + 8))) = pack8(v2, v3);
    }
    CP_WAIT(0);
    __syncthreads();

    // ---------------- GEMM1': xe[64,64] @ B1^T -> frag [64,128] ----------------
    float c1[2][4][4];
#pragma unroll
    for (int a = 0; a < 2; a++)
#pragma unroll
        for (int b = 0; b < 4; b++)
#pragma unroll
            for (int d = 0; d < 4; d++) c1[a][b][d] = 0.f;

#pragma unroll
    for (int ks = 0; ks < 4; ks++) {
        const uint32_t kb = ks * 16;
        uint32_t a4[2][4];
#pragma unroll
        for (int mf = 0; mf < 2; mf++) {
            uint32_t r = (uint32_t)(mw * 32 + mf * 16) + la_r;
            ldsm_x4(a4[mf], sb + panel_off(r, kb + la_kb));
        }
#pragma unroll
        for (int np = 0; np < 2; np++) {
            uint32_t n = (uint32_t)(nw * 32 + np * 16) + lb_r;
            uint32_t b4[4];
            ldsm_x4(b4, sb + 8192u + panel_off(n, kb + lb_kb));
#pragma unroll
            for (int mf = 0; mf < 2; mf++) {
                MMA16816(c1[mf][np * 2],     a4[mf], b4);
                MMA16816(c1[mf][np * 2 + 1], a4[mf], b4 + 2);
            }
        }
    }
    __syncthreads();   // A + B1 consumed; h panels may overwrite

    // ---- Epilogue1 (fragment layout): c1 + Ps + Pr + bias -> SiLU -> h panels ----
    {
        const int l4 = lane >> 2;
        const int l2 = (lane & 3) * 2;
#pragma unroll
        for (int nf = 0; nf < 4; nf++) {
            int col = nw * 32 + nf * 8 + l2;
            float b0 = __ldg(eb1 + col), b1 = __ldg(eb1 + col + 1);
            const uint32_t hpan = (uint32_t)(col >> 6) * 8192u;
            const uint32_t kk = (uint32_t)(col & 63);
#pragma unroll
            for (int mf = 0; mf < 2; mf++) {
#pragma unroll
                for (int half = 0; half < 2; half++) {
                    uint32_t row = (uint32_t)(mw * 32 + mf * 16 + l4 + half * 8);
                    __half2 hs = *(__half2*)(dsm + 40960u + row * 272 + col * 2);
                    __half2 hr = *(__half2*)(dsm + 58368u + row * 272 + col * 2);
                    float x0 = silu_f(c1[mf][nf][half * 2]     + __low2float(hs)  + __low2float(hr)  + b0);
                    float x1 = silu_f(c1[mf][nf][half * 2 + 1] + __high2float(hs) + __high2float(hr) + b1);
                    *(uint32_t*)(dsm + hpan + panel_off(row, kk)) = f16x2(x0, x1);
                }
            }
        }
    }
    __syncthreads();

    // ---------------- GEMM2: h[64,128] @ eW2t^T -> [64,64] ----------------
    float c2[2][2][4];
#pragma unroll
    for (int a = 0; a < 2; a++)
#pragma unroll
        for (int b = 0; b < 2; b++)
#pragma unroll
            for (int d = 0; d < 4; d++) c2[a][b][d] = 0.f;

#pragma unroll
    for (int p = 0; p < 2; p++) {
        const uint32_t Ap = sb + (uint32_t)p * 8192u;
        const uint32_t Bp = sb + 24576u + (uint32_t)p * 8192u;
#pragma unroll
        for (int ks = 0; ks < 4; ks++) {
            const uint32_t kb = ks * 16;
            uint32_t a4[2][4];
#pragma unroll
            for (int mf = 0; mf < 2; mf++) {
                uint32_t r = (uint32_t)(mw * 32 + mf * 16) + la_r;
                ldsm_x4(a4[mf], Ap + panel_off(r, kb + la_kb));
            }
            uint32_t n = (uint32_t)(nw * 16) + lb_r;
            uint32_t b4[4];
            ldsm_x4(b4, Bp + panel_off(n, kb + lb_kb));
#pragma unroll
            for (int mf = 0; mf < 2; mf++) {
                MMA16816(c2[mf][0], a4[mf], b4);
                MMA16816(c2[mf][1], a4[mf], b4 + 2);
            }
        }
    }

    // ---------------- Epilogue2: SiLU, store, scatter-add ----------------
    {
        const int l4 = lane >> 2;
        const int l2 = (lane & 3) * 2;
        float b0[2], b1[2];
#pragma unroll
        for (int nf = 0; nf < 2; nf++) {
            int col = nw * 16 + nf * 8 + l2;
            b0[nf] = __ldg(eb2 + col);
            b1[nf] = __ldg(eb2 + col + 1);
        }
#pragma unroll
        for (int mf = 0; mf < 2; mf++) {
#pragma unroll
            for (int half = 0; half < 2; half++) {
                int m = mw * 32 + mf * 16 + l4 + half * 8;
                int rcv = s_rcv[m];
                float* orow = edges_out + (size_t)(e0 + m) * EDGE_C;
                float* arow = g_aggr + (size_t)rcv * EDGE_C;
#pragma unroll
                for (int nf = 0; nf < 2; nf++) {
                    int col = nw * 16 + nf * 8 + l2;
                    float o0 = silu_f(c2[mf][nf][half * 2]     + b0[nf]);
                    float o1 = silu_f(c2[mf][nf][half * 2 + 1] + b1[nf]);
                    float2 ov = {o0, o1};
                    *reinterpret_cast<float2*>(orow + col) = ov;
                    atomicAdd(arow + col,     o0);
                    atomicAdd(arow + col + 1, o1);
                }
            }
        }
    }
}

// ---------------------------------------------------------------------------
// Node kernel: 64 nodes / CTA, 256 threads, 2 CTAs/SM (R13 verbatim)
// ---------------------------------------------------------------------------
__global__ __launch_bounds__(256, 2)
void node_mma_kernel(const float* __restrict__ xn,
                     const float* __restrict__ nb1,
                     const float* __restrict__ nb2,
                     float* __restrict__ nodes_out)
{
    extern __shared__ __align__(1024) char dsm[];

    const int tid  = threadIdx.x;
    const int wid  = tid >> 5;
    const int lane = tid & 31;
    const int mw   = wid & 1;
    const int nw   = wid >> 1;
    const int m0   = blockIdx.x * 64;

    const uint32_t sb = smem_u32(dsm);
    const uint32_t la_r  = lane & 15;
    const uint32_t la_kb = (lane >> 4) << 3;
    const uint32_t lb_r  = (lane & 7) | ((lane >> 4) << 3);
    const uint32_t lb_kb = ((lane >> 3) & 1) << 3;

    const int gm = tid >> 2;
    const int gq = tid & 3;
    const int bn = tid >> 1;
    const int bq = tid & 1;
    const size_t grow = (size_t)m0 + gm;
    const bool gvalid = grow < N_NODES;

    {
        const __half* s = g_nW1t + (size_t)bn * 192 + bq * 32;
#pragma unroll
        for (int j = 0; j < 4; j++) {
            uint32_t off = panel_off((uint32_t)bn, (uint32_t)(bq * 32 + j * 8));
            cp16(sb + 8192u + off, s + j * 8);
        }
        CP_COMMIT();
    }
    float4 av[4];
    {
        const float4* rp = reinterpret_cast<const float4*>(xn + grow * NODE_C) + gq * 4;
#pragma unroll
        for (int i = 0; i < 4; i++)
            av[i] = gvalid ? rp[i] : make_float4(0.f, 0.f, 0.f, 0.f);
    }

    float c[2][4][4];
#pragma unroll
    for (int a = 0; a < 2; a++)
#pragma unroll
        for (int b = 0; b < 4; b++)
#pragma unroll
            for (int d = 0; d < 4; d++) c[a][b][d] = 0.f;

#pragma unroll 1
    for (int ch = 0; ch < 3; ch++) {
        __syncthreads();
#pragma unroll
        for (int i = 0; i < 2; i++) {
            uint32_t off = panel_off((uint32_t)gm, (uint32_t)(gq * 16 + i * 8));
            *(uint4*)(dsm + off) = pack8(av[2 * i], av[2 * i + 1]);
        }
        if (ch < 2) {
            const int nc = ch + 1;
            uint32_t dst = 8192u + (uint32_t)((nc & 1) * 16384);
            const __half* s = g_nW1t + (size_t)bn * 192 + nc * 64 + bq * 32;
#pragma unroll
            for (int j = 0; j < 4; j++) {
                uint32_t off = panel_off((uint32_t)bn, (uint32_t)(bq * 32 + j * 8));
                cp16(sb + dst + off, s + j * 8);
            }
            CP_COMMIT();
            const float* rowp = (nc < 2) ? xn + grow * NODE_C + nc * 64
                                         : g_aggr + grow * EDGE_C;
            const float4* rp = reinterpret_cast<const float4*>(rowp) + gq * 4;
#pragma unroll
            for (int i = 0; i < 4; i++)
                av[i] = gvalid ? rp[i] : make_float4(0.f, 0.f, 0.f, 0.f);
        } else {
            const __half* s = g_nW2t + (size_t)bn * 128;
#pragma unroll
            for (int j = 0; j < 8; j++) {
                int seg = bq * 8 + j;
                uint32_t p = (uint32_t)(seg >> 3);
                uint32_t off = p * 16384u + panel_off((uint32_t)bn, (uint32_t)((seg & 7) * 8));
                cp16(sb + 40960u + off, s + seg * 8);
            }
            CP_COMMIT();
        }
        CP_WAIT(1);
        __syncthreads();

        const uint32_t Bp = sb + 8192u + (uint32_t)((ch & 1) * 16384);
#pragma unroll
        for (int ks = 0; ks < 4; ks++) {
            const uint32_t kb = ks * 16;
            uint32_t a4[2][4];
#pragma unroll
            for (int mf = 0; mf < 2; mf++) {
                uint32_t r = (uint32_t)(mw * 32 + mf * 16) + la_r;
                ldsm_x4(a4[mf], sb + panel_off(r, kb + la_kb));
            }
#pragma unroll
            for (int np = 0; np < 2; np++) {
                uint32_t n = (uint32_t)(nw * 32 + np * 16) + lb_r;
                uint32_t b4[4];
                ldsm_x4(b4, Bp + panel_off(n, kb + lb_kb));
#pragma unroll
                for (int mf = 0; mf < 2; mf++) {
                    MMA16816(c[mf][np * 2],     a4[mf], b4);
                    MMA16816(c[mf][np * 2 + 1], a4[mf], b4 + 2);
                }
            }
        }
    }
    __syncthreads();

    {
        const int l4 = lane >> 2;
        const int l2 = (lane & 3) * 2;
        const uint32_t hb = (uint32_t)(nw >> 1) * 8192u;
#pragma unroll
        for (int nf = 0; nf < 4; nf++) {
            int col = nw * 32 + nf * 8 + l2;
            float b0 = __ldg(nb1 + col), b1 = __ldg(nb1 + col + 1);
            uint32_t kk = (uint32_t)((nw & 1) * 32 + nf * 8 + l2);
#pragma unroll
            for (int mf = 0; mf < 2; mf++) {
                uint32_t m = (uint32_t)(mw * 32 + mf * 16 + l4);
                float x0 = silu_f(c[mf][nf][0] + b0);
                float x1 = silu_f(c[mf][nf][1] + b1);
                float x2 = silu_f(c[mf][nf][2] + b0);
                float x3 = silu_f(c[mf][nf][3] + b1);
                *(uint32_t*)(dsm + hb + panel_off(m, kk))     = f16x2(x0, x1);
                *(uint32_t*)(dsm + hb + panel_off(m + 8, kk)) = f16x2(x2, x3);
            }
        }
    }
    CP_WAIT(0);
    __syncthreads();

    float c2[2][4][4];
#pragma unroll
    for (int a = 0; a < 2; a++)
#pragma unroll
        for (int b = 0; b < 4; b++)
#pragma unroll
            for (int d = 0; d < 4; d++) c2[a][b][d] = 0.f;

#pragma unroll
    for (int p = 0; p < 2; p++) {
        const uint32_t Ap = sb + (uint32_t)p * 8192u;
        const uint32_t Bp = sb + 40960u + (uint32_t)p * 16384u;
#pragma unroll
        for (int ks = 0; ks < 4; ks++) {
            const uint32_t kb = ks * 16;
            uint32_t a4[2][4];
#pragma unroll
            for (int mf = 0; mf < 2; mf++) {
                uint32_t r = (uint32_t)(mw * 32 + mf * 16) + la_r;
                ldsm_x4(a4[mf], Ap + panel_off(r, kb + la_kb));
            }
#pragma unroll
            for (int np = 0; np < 2; np++) {
                uint32_t n = (uint32_t)(nw * 32 + np * 16) + lb_r;
                uint32_t b4[4];
                ldsm_x4(b4, Bp + panel_off(n, kb + lb_kb));
#pragma unroll
                for (int mf = 0; mf < 2; mf++) {
                    MMA16816(c2[mf][np * 2],     a4[mf], b4);
                    MMA16816(c2[mf][np * 2 + 1], a4[mf], b4 + 2);
                }
            }
        }
    }

    {
        const int l4 = lane >> 2;
        const int l2 = (lane & 3) * 2;
        float b0[4], b1[4];
#pragma unroll
        for (int nf = 0; nf < 4; nf++) {
            int col = nw * 32 + nf * 8 + l2;
            b0[nf] = __ldg(nb2 + col);
            b1[nf] = __ldg(nb2 + col + 1);
        }
#pragma unroll
        for (int mf = 0; mf < 2; mf++) {
#pragma unroll
            for (int half = 0; half < 2; half++) {
                size_t row = (size_t)m0 + mw * 32 + mf * 16 + l4 + half * 8;
                if (row < N_NODES) {
                    float* orow = nodes_out + row * NODE_C;
#pragma unroll
                    for (int nf = 0; nf < 4; nf++) {
                        int col = nw * 32 + nf * 8 + l2;
                        float2 ov;
                        ov.x = c2[mf][nf][half * 2]     + b0[nf];
                        ov.y = c2[mf][nf][half * 2 + 1] + b1[nf];
                        *reinterpret_cast<float2*>(orow + col) = ov;
                    }
                }
            }
        }
    }
}

// ---------------------------------------------------------------------------
extern "C" void kernel_launch(void* const* d_in, const int* in_sizes, int n_in,
                              void* d_out, int out_size)
{
    const float* xn   = (const float*)d_in[0];
    const float* xe   = (const float*)d_in[1];
    const void*  eidx =               d_in[2];
    const float* eW1  = (const float*)d_in[3];
    const float* eb1  = (const float*)d_in[4];
    const float* eW2  = (const float*)d_in[5];
    const float* eb2  = (const float*)d_in[6];
    const float* nW1  = (const float*)d_in[7];
    const float* nb1  = (const float*)d_in[8];
    const float* nW2  = (const float*)d_in[9];
    const float* nb2  = (const float*)d_in[10];

    float* nodes_out = (float*)d_out;
    float* edges_out = (float*)d_out + (size_t)N_NODES * NODE_C;

    cudaFuncSetAttribute(precompute_P_kernel, cudaFuncAttributeMaxDynamicSharedMemorySize, PREP_P_SMEM);
    cudaFuncSetAttribute(edge_mma_kernel, cudaFuncAttributeMaxDynamicSharedMemorySize, EDGE_SMEM);
    cudaFuncSetAttribute(node_mma_kernel, cudaFuncAttributeMaxDynamicSharedMemorySize, NODE_SMEM);

    prep_kernel<<<9535, 256>>>(xn, eW1, eW2, nW1, nW2);
    precompute_P_kernel<<<(N_NODES + 127) / 128, 256, PREP_P_SMEM>>>();
    edge_mma_kernel<<<N_EDGES / 64, 256, EDGE_SMEM>>>(xe, eidx, eb1, eb2, edges_out);
    node_mma_kernel<<<(N_NODES + 63) / 64, 256, NODE_SMEM>>>(xn, nb1, nb2, nodes_out);
}

// round 16
// speedup vs baseline: 1.3551x; 1.0208x over previous
#include <cuda_runtime.h>
#include <cuda_fp16.h>
#include <cstdint>

#define N_NODES 50000
#define N_EDGES 800000
#define NODE_C  128
#define EDGE_C  64

// ---------------------------------------------------------------------------
// Device scratch (no cudaMalloc allowed)
// ---------------------------------------------------------------------------
__device__ float g_aggr[(size_t)N_NODES * EDGE_C];
// P (fp16): [n][0:128]=xn@eW1[0:128], [n][128:256]=xn@eW1[128:256]
__device__ __align__(16) __half g_P_h[(size_t)N_NODES * 256];
__device__ __align__(16) __half g_xn_h[(size_t)N_NODES * NODE_C];
__device__ __align__(16) __half g_eW1t[128 * 320];
__device__ __align__(16) __half g_eW2t[64 * 128];
__device__ __align__(16) __half g_nW1t[128 * 192];
__device__ __align__(16) __half g_nW2t[128 * 128];

// ---------------------------------------------------------------------------
// Helpers
// ---------------------------------------------------------------------------
__device__ __forceinline__ uint32_t smem_u32(const void* p) {
    uint32_t a;
    asm("{ .reg .u64 t; cvta.to.shared.u64 t, %1; cvt.u32.u64 %0, t; }"
        : "=r"(a) : "l"(p));
    return a;
}

// Panels: [rows][64] fp16, 128-byte rows, XOR-swizzled 16B blocks.
__device__ __forceinline__ uint32_t panel_off(uint32_t r, uint32_t k) {
    return r * 128u + ((((k >> 3) ^ (r & 7u)) << 4) | ((k & 7u) << 1));
}

__device__ __forceinline__ void ldsm_x4(uint32_t* d, uint32_t a) {
    asm volatile("ldmatrix.sync.aligned.m8n8.x4.shared.b16 {%0,%1,%2,%3}, [%4];"
                 : "=r"(d[0]), "=r"(d[1]), "=r"(d[2]), "=r"(d[3]) : "r"(a));
}

#define MMA16816(c, a, b) \
    asm volatile("mma.sync.aligned.m16n8k16.row.col.f32.f16.f16.f32 " \
        "{%0,%1,%2,%3},{%4,%5,%6,%7},{%8,%9},{%0,%1,%2,%3};" \
        : "+f"((c)[0]), "+f"((c)[1]), "+f"((c)[2]), "+f"((c)[3]) \
        : "r"((a)[0]), "r"((a)[1]), "r"((a)[2]), "r"((a)[3]), \
          "r"((b)[0]), "r"((b)[1]))

__device__ __forceinline__ void cp16(uint32_t dst, const void* src) {
    asm volatile("cp.async.cg.shared.global [%0], [%1], 16;"
                 :: "r"(dst), "l"(src) : "memory");
}
#define CP_COMMIT() asm volatile("cp.async.commit_group;" ::: "memory")
#define CP_WAIT(n)  asm volatile("cp.async.wait_group %0;" :: "n"(n) : "memory")

__device__ __forceinline__ void red2(float* p, float2 v) {
    asm volatile("red.global.add.v2.f32 [%0], {%1,%2};"
                 :: "l"(p), "f"(v.x), "f"(v.y) : "memory");
}

__device__ __forceinline__ uint32_t f16x2(float lo, float hi) {
    uint32_t r;
    asm("cvt.rn.f16x2.f32 %0, %1, %2;" : "=r"(r) : "f"(hi), "f"(lo));
    return r;
}
__device__ __forceinline__ float silu_f(float x) {
    return x / (1.0f + __expf(-x));
}
__device__ __forceinline__ uint4 pack8(float4 v0, float4 v1) {
    uint4 r;
    r.x = f16x2(v0.x, v0.y);
    r.y = f16x2(v0.z, v0.w);
    r.z = f16x2(v1.x, v1.y);
    r.w = f16x2(v1.z, v1.w);
    return r;
}

// ---------------------------------------------------------------------------
// Fused prep (R13 verbatim)
// ---------------------------------------------------------------------------
__global__ void prep_kernel(const float* __restrict__ xn,
                            const float* __restrict__ eW1,
                            const float* __restrict__ eW2,
                            const float* __restrict__ nW1,
                            const float* __restrict__ nW2) {
    int b = blockIdx.x;
    if (b < 3125) {
        size_t i = (size_t)b * 256 + threadIdx.x;
        if (i < (size_t)N_NODES * EDGE_C / 4)
            reinterpret_cast<float4*>(g_aggr)[i] = make_float4(0.f, 0.f, 0.f, 0.f);
    } else if (b < 9375) {
        size_t i = (size_t)(b - 3125) * 256 + threadIdx.x;
        if (i < (size_t)N_NODES * NODE_C / 4) {
            float4 v = reinterpret_cast<const float4*>(xn)[i];
            uint2 h;
            h.x = f16x2(v.x, v.y);
            h.y = f16x2(v.z, v.w);
            reinterpret_cast<uint2*>(g_xn_h)[i] = h;
        }
    } else {
        int i = (b - 9375) * 256 + threadIdx.x;
        if (i < 128 * 320) {
            int n = i / 320, k = i % 320;
            g_eW1t[i] = __float2half_rn(eW1[(size_t)k * 128 + n]);
        }
        if (i < 64 * 128) {
            int n = i / 128, k = i % 128;
            g_eW2t[i] = __float2half_rn(eW2[(size_t)k * 64 + n]);
        }
        if (i < 128 * 192) {
            int n = i / 192, k = i % 192;
            g_nW1t[i] = __float2half_rn(nW1[(size_t)k * 128 + n]);
        }
        if (i < 128 * 128) {
            int n = i / 128, k = i % 128;
            g_nW2t[i] = __float2half_rn(nW2[(size_t)k * 128 + n]);
        }
    }
}

// ---------------------------------------------------------------------------
// Precompute P (fp16 output): [50k,128] @ [128,256]  (R15 verbatim)
// ---------------------------------------------------------------------------
#define PREP_P_SMEM 98304

__global__ __launch_bounds__(256, 2)
void precompute_P_kernel() {
    extern __shared__ __align__(1024) char dsm[];
    const int tid  = threadIdx.x;
    const int wid  = tid >> 5;
    const int lane = tid & 31;
    const int mw   = wid & 3;
    const int nw   = wid >> 2;
    const int m0   = blockIdx.x * 128;

    const uint32_t sb = smem_u32(dsm);
    const uint32_t la_r  = lane & 15;
    const uint32_t la_kb = (lane >> 4) << 3;
    const uint32_t lb_r  = (lane & 7) | ((lane >> 4) << 3);
    const uint32_t lb_kb = ((lane >> 3) & 1) << 3;

    {
        const int r = tid >> 1;
        const int half = tid & 1;
        const size_t node = (size_t)m0 + r;
        if (node < N_NODES) {
            const __half* a = g_xn_h + node * NODE_C + half * 64;
#pragma unroll
            for (int j = 0; j < 8; j++)
                cp16(sb + (uint32_t)(half * 16384) + panel_off((uint32_t)r, (uint32_t)(j * 8)), a + j * 8);
        } else {
            uint4 z = {0, 0, 0, 0};
#pragma unroll
            for (int j = 0; j < 8; j++)
                *(uint4*)(dsm + half * 16384 + panel_off((uint32_t)r, (uint32_t)(j * 8))) = z;
        }
    }
    {
        const int n = tid >> 1;
        const int hb = tid & 1;
#pragma unroll
        for (int kc2 = 0; kc2 < 2; kc2++) {
            int kc = hb * 2 + kc2;
            const __half* s = g_eW1t + (size_t)n * 320 + kc * 64;
#pragma unroll
            for (int j = 0; j < 8; j++)
                cp16(sb + 32768u + (uint32_t)(kc * 16384) + panel_off((uint32_t)n, (uint32_t)(j * 8)), s + j * 8);
        }
    }
    CP_COMMIT();
    CP_WAIT(0);
    __syncthreads();

#pragma unroll 1
    for (int o = 0; o < 2; o++) {
        float c[2][8][4];
#pragma unroll
        for (int a = 0; a < 2; a++)
#pragma unroll
            for (int b = 0; b < 8; b++)
#pragma unroll
                for (int d = 0; d < 4; d++) c[a][b][d] = 0.f;

#pragma unroll
        for (int p = 0; p < 2; p++) {
            const uint32_t Ap = sb + (uint32_t)p * 16384u;
            const uint32_t Bp = sb + 32768u + (uint32_t)(o * 2 + p) * 16384u;
#pragma unroll
            for (int ks = 0; ks < 4; ks++) {
                const uint32_t kb = ks * 16;
                uint32_t a4[2][4];
#pragma unroll
                for (int mf = 0; mf < 2; mf++) {
                    uint32_t r = (uint32_t)(mw * 32 + mf * 16) + la_r;
                    ldsm_x4(a4[mf], Ap + panel_off(r, kb + la_kb));
                }
#pragma unroll
                for (int np = 0; np < 4; np++) {
                    uint32_t n = (uint32_t)(nw * 64 + np * 16) + lb_r;
                    uint32_t b4[4];
                    ldsm_x4(b4, Bp + panel_off(n, kb + lb_kb));
#pragma unroll
                    for (int mf = 0; mf < 2; mf++) {
                        MMA16816(c[mf][np * 2],     a4[mf], b4);
                        MMA16816(c[mf][np * 2 + 1], a4[mf], b4 + 2);
                    }
                }
            }
        }
        const int l4 = lane >> 2;
        const int l2 = (lane & 3) * 2;
#pragma unroll
        for (int mf = 0; mf < 2; mf++) {
#pragma unroll
            for (int half = 0; half < 2; half++) {
                size_t node = (size_t)m0 + mw * 32 + mf * 16 + l4 + half * 8;
                if (node < N_NODES) {
                    __half* prow = g_P_h + node * 256 + o * 128;
#pragma unroll
                    for (int nf = 0; nf < 8; nf++) {
                        int col = nw * 64 + nf * 8 + l2;
                        *(uint32_t*)(prow + col) = f16x2(c[mf][nf][half * 2], c[mf][nf][half * 2 + 1]);
                    }
                }
            }
        }
    }
}

// ---------------------------------------------------------------------------
// Edge kernel (R15, epilogue2 atomics -> red.v2): 64 edges / CTA, 256 threads
// ---------------------------------------------------------------------------
#define EDGE_SMEM 75776
#define NODE_SMEM 73728

__global__ __launch_bounds__(256, 2)
void edge_mma_kernel(const float* __restrict__ xe,
                     const void*  __restrict__ eidx,
                     const float* __restrict__ eb1,
                     const float* __restrict__ eb2,
                     float* __restrict__ edges_out)
{
    extern __shared__ __align__(1024) char dsm[];
    __shared__ int s_snd[64], s_rcv[64];

    const int tid  = threadIdx.x;
    const int wid  = tid >> 5;
    const int lane = tid & 31;
    const int mw   = wid & 1;
    const int nw   = wid >> 1;
    const int e0   = blockIdx.x * 64;

    const uint32_t sb = smem_u32(dsm);
    const uint32_t la_r  = lane & 15;
    const uint32_t la_kb = (lane >> 4) << 3;
    const uint32_t lb_r  = (lane & 7) | ((lane >> 4) << 3);
    const uint32_t lb_kb = ((lane >> 3) & 1) << 3;

    // edge indices
    {
        const unsigned* w = reinterpret_cast<const unsigned*>(eidx);
        const bool is64 = ((w[1] | w[3] | w[5] | w[7] | w[9] | w[11] | w[13] | w[15]) == 0u);
        if (tid < 64) {
            size_t e = (size_t)e0 + tid;
            if (is64) {
                const long long* p = reinterpret_cast<const long long*>(eidx);
                s_snd[tid] = (int)p[e];
                s_rcv[tid] = (int)p[(size_t)N_EDGES + e];
            } else {
                const int* p = reinterpret_cast<const int*>(eidx);
                s_snd[tid] = p[e];
                s_rcv[tid] = p[(size_t)N_EDGES + e];
            }
        }
    }
    __syncthreads();

    // cp.async group: B1 + B2 + Ps + Pr
    {
        const int n = tid >> 1;
        const int bq = tid & 1;
        const __half* s = g_eW1t + (size_t)n * 320 + 256 + bq * 32;
#pragma unroll
        for (int j = 0; j < 4; j++)
            cp16(sb + 8192u + panel_off((uint32_t)n, (uint32_t)(bq * 32 + j * 8)), s + j * 8);

        const int n2 = tid >> 2;
        const int q2 = tid & 3;
        const __half* s2 = g_eW2t + (size_t)n2 * 128;
#pragma unroll
        for (int j = 0; j < 4; j++) {
            int seg = q2 * 4 + j;
            uint32_t p = (uint32_t)(seg >> 3);
            cp16(sb + 24576u + p * 8192u + panel_off((uint32_t)n2, (uint32_t)((seg & 7) * 8)), s2 + seg * 8);
        }

        const int prow = tid >> 2;
        const int pq   = tid & 3;
        const __half* ps = g_P_h + (size_t)s_snd[prow] * 256 + pq * 32;
        const __half* pr = g_P_h + (size_t)s_rcv[prow] * 256 + 128 + pq * 32;
        uint32_t pbase = (uint32_t)(prow * 272 + pq * 64);
#pragma unroll
        for (int j = 0; j < 4; j++) {
            cp16(sb + 40960u + pbase + j * 16, ps + j * 8);
            cp16(sb + 58368u + pbase + j * 16, pr + j * 8);
        }
        CP_COMMIT();
    }
    // xe -> fp16 panel @0
    {
        const int row = tid >> 2;
        const int q   = tid & 3;
        const float4* rp = reinterpret_cast<const float4*>(xe + (size_t)(e0 + row) * EDGE_C) + q * 4;
        float4 v0 = rp[0], v1 = rp[1], v2 = rp[2], v3 = rp[3];
        *(uint4*)(dsm + panel_off((uint32_t)row, (uint32_t)(q * 16)))     = pack8(v0, v1);
        *(uint4*)(dsm + panel_off((uint32_t)row, (uint32_t)(q * 16 + 8))) = pack8(v2, v3);
    }
    CP_WAIT(0);
    __syncthreads();

    // ---------------- GEMM1': xe[64,64] @ B1^T -> frag [64,128] ----------------
    float c1[2][4][4];
#pragma unroll
    for (int a = 0; a < 2; a++)
#pragma unroll
        for (int b = 0; b < 4; b++)
#pragma unroll
            for (int d = 0; d < 4; d++) c1[a][b][d] = 0.f;

#pragma unroll
    for (int ks = 0; ks < 4; ks++) {
        const uint32_t kb = ks * 16;
        uint32_t a4[2][4];
#pragma unroll
        for (int mf = 0; mf < 2; mf++) {
            uint32_t r = (uint32_t)(mw * 32 + mf * 16) + la_r;
            ldsm_x4(a4[mf], sb + panel_off(r, kb + la_kb));
        }
#pragma unroll
        for (int np = 0; np < 2; np++) {
            uint32_t n = (uint32_t)(nw * 32 + np * 16) + lb_r;
            uint32_t b4[4];
            ldsm_x4(b4, sb + 8192u + panel_off(n, kb + lb_kb));
#pragma unroll
            for (int mf = 0; mf < 2; mf++) {
                MMA16816(c1[mf][np * 2],     a4[mf], b4);
                MMA16816(c1[mf][np * 2 + 1], a4[mf], b4 + 2);
            }
        }
    }
    __syncthreads();

    // ---- Epilogue1 (fragment layout): c1 + Ps + Pr + bias -> SiLU -> h panels ----
    {
        const int l4 = lane >> 2;
        const int l2 = (lane & 3) * 2;
#pragma unroll
        for (int nf = 0; nf < 4; nf++) {
            int col = nw * 32 + nf * 8 + l2;
            float b0 = __ldg(eb1 + col), b1 = __ldg(eb1 + col + 1);
            const uint32_t hpan = (uint32_t)(col >> 6) * 8192u;
            const uint32_t kk = (uint32_t)(col & 63);
#pragma unroll
            for (int mf = 0; mf < 2; mf++) {
#pragma unroll
                for (int half = 0; half < 2; half++) {
                    uint32_t row = (uint32_t)(mw * 32 + mf * 16 + l4 + half * 8);
                    __half2 hs = *(__half2*)(dsm + 40960u + row * 272 + col * 2);
                    __half2 hr = *(__half2*)(dsm + 58368u + row * 272 + col * 2);
                    float x0 = silu_f(c1[mf][nf][half * 2]     + __low2float(hs)  + __low2float(hr)  + b0);
                    float x1 = silu_f(c1[mf][nf][half * 2 + 1] + __high2float(hs) + __high2float(hr) + b1);
                    *(uint32_t*)(dsm + hpan + panel_off(row, kk)) = f16x2(x0, x1);
                }
            }
        }
    }
    __syncthreads();

    // ---------------- GEMM2: h[64,128] @ eW2t^T -> [64,64] ----------------
    float c2[2][2][4];
#pragma unroll
    for (int a = 0; a < 2; a++)
#pragma unroll
        for (int b = 0; b < 2; b++)
#pragma unroll
            for (int d = 0; d < 4; d++) c2[a][b][d] = 0.f;

#pragma unroll
    for (int p = 0; p < 2; p++) {
        const uint32_t Ap = sb + (uint32_t)p * 8192u;
        const uint32_t Bp = sb + 24576u + (uint32_t)p * 8192u;
#pragma unroll
        for (int ks = 0; ks < 4; ks++) {
            const uint32_t kb = ks * 16;
            uint32_t a4[2][4];
#pragma unroll
            for (int mf = 0; mf < 2; mf++) {
                uint32_t r = (uint32_t)(mw * 32 + mf * 16) + la_r;
                ldsm_x4(a4[mf], Ap + panel_off(r, kb + la_kb));
            }
            uint32_t n = (uint32_t)(nw * 16) + lb_r;
            uint32_t b4[4];
            ldsm_x4(b4, Bp + panel_off(n, kb + lb_kb));
#pragma unroll
            for (int mf = 0; mf < 2; mf++) {
                MMA16816(c2[mf][0], a4[mf], b4);
                MMA16816(c2[mf][1], a4[mf], b4 + 2);
            }
        }
    }

    // ---------------- Epilogue2: SiLU, store, red.v2 scatter-add ----------------
    {
        const int l4 = lane >> 2;
        const int l2 = (lane & 3) * 2;
        float b0[2], b1[2];
#pragma unroll
        for (int nf = 0; nf < 2; nf++) {
            int col = nw * 16 + nf * 8 + l2;
            b0[nf] = __ldg(eb2 + col);
            b1[nf] = __ldg(eb2 + col + 1);
        }
#pragma unroll
        for (int mf = 0; mf < 2; mf++) {
#pragma unroll
            for (int half = 0; half < 2; half++) {
                int m = mw * 32 + mf * 16 + l4 + half * 8;
                int rcv = s_rcv[m];
                float* orow = edges_out + (size_t)(e0 + m) * EDGE_C;
                float* arow = g_aggr + (size_t)rcv * EDGE_C;
#pragma unroll
                for (int nf = 0; nf < 2; nf++) {
                    int col = nw * 16 + nf * 8 + l2;
                    float o0 = silu_f(c2[mf][nf][half * 2]     + b0[nf]);
                    float o1 = silu_f(c2[mf][nf][half * 2 + 1] + b1[nf]);
                    float2 ov = {o0, o1};
                    *reinterpret_cast<float2*>(orow + col) = ov;
                    red2(arow + col, ov);
                }
            }
        }
    }
}

// ---------------------------------------------------------------------------
// Node kernel: 64 nodes / CTA, 256 threads, 2 CTAs/SM (R13 verbatim)
// ---------------------------------------------------------------------------
__global__ __launch_bounds__(256, 2)
void node_mma_kernel(const float* __restrict__ xn,
                     const float* __restrict__ nb1,
                     const float* __restrict__ nb2,
                     float* __restrict__ nodes_out)
{
    extern __shared__ __align__(1024) char dsm[];

    const int tid  = threadIdx.x;
    const int wid  = tid >> 5;
    const int lane = tid & 31;
    const int mw   = wid & 1;
    const int nw   = wid >> 1;
    const int m0   = blockIdx.x * 64;

    const uint32_t sb = smem_u32(dsm);
    const uint32_t la_r  = lane & 15;
    const uint32_t la_kb = (lane >> 4) << 3;
    const uint32_t lb_r  = (lane & 7) | ((lane >> 4) << 3);
    const uint32_t lb_kb = ((lane >> 3) & 1) << 3;

    const int gm = tid >> 2;
    const int gq = tid & 3;
    const int bn = tid >> 1;
    const int bq = tid & 1;
    const size_t grow = (size_t)m0 + gm;
    const bool gvalid = grow < N_NODES;

    {
        const __half* s = g_nW1t + (size_t)bn * 192 + bq * 32;
#pragma unroll
        for (int j = 0; j < 4; j++) {
            uint32_t off = panel_off((uint32_t)bn, (uint32_t)(bq * 32 + j * 8));
            cp16(sb + 8192u + off, s + j * 8);
        }
        CP_COMMIT();
    }
    float4 av[4];
    {
        const float4* rp = reinterpret_cast<const float4*>(xn + grow * NODE_C) + gq * 4;
#pragma unroll
        for (int i = 0; i < 4; i++)
            av[i] = gvalid ? rp[i] : make_float4(0.f, 0.f, 0.f, 0.f);
    }

    float c[2][4][4];
#pragma unroll
    for (int a = 0; a < 2; a++)
#pragma unroll
        for (int b = 0; b < 4; b++)
#pragma unroll
            for (int d = 0; d < 4; d++) c[a][b][d] = 0.f;

#pragma unroll 1
    for (int ch = 0; ch < 3; ch++) {
        __syncthreads();
#pragma unroll
        for (int i = 0; i < 2; i++) {
            uint32_t off = panel_off((uint32_t)gm, (uint32_t)(gq * 16 + i * 8));
            *(uint4*)(dsm + off) = pack8(av[2 * i], av[2 * i + 1]);
        }
        if (ch < 2) {
            const int nc = ch + 1;
            uint32_t dst = 8192u + (uint32_t)((nc & 1) * 16384);
            const __half* s = g_nW1t + (size_t)bn * 192 + nc * 64 + bq * 32;
#pragma unroll
            for (int j = 0; j < 4; j++) {
                uint32_t off = panel_off((uint32_t)bn, (uint32_t)(bq * 32 + j * 8));
                cp16(sb + dst + off, s + j * 8);
            }
            CP_COMMIT();
            const float* rowp = (nc < 2) ? xn + grow * NODE_C + nc * 64
                                         : g_aggr + grow * EDGE_C;
            const float4* rp = reinterpret_cast<const float4*>(rowp) + gq * 4;
#pragma unroll
            for (int i = 0; i < 4; i++)
                av[i] = gvalid ? rp[i] : make_float4(0.f, 0.f, 0.f, 0.f);
        } else {
            const __half* s = g_nW2t + (size_t)bn * 128;
#pragma unroll
            for (int j = 0; j < 8; j++) {
                int seg = bq * 8 + j;
                uint32_t p = (uint32_t)(seg >> 3);
                uint32_t off = p * 16384u + panel_off((uint32_t)bn, (uint32_t)((seg & 7) * 8));
                cp16(sb + 40960u + off, s + seg * 8);
            }
            CP_COMMIT();
        }
        CP_WAIT(1);
        __syncthreads();

        const uint32_t Bp = sb + 8192u + (uint32_t)((ch & 1) * 16384);
#pragma unroll
        for (int ks = 0; ks < 4; ks++) {
            const uint32_t kb = ks * 16;
            uint32_t a4[2][4];
#pragma unroll
            for (int mf = 0; mf < 2; mf++) {
                uint32_t r = (uint32_t)(mw * 32 + mf * 16) + la_r;
                ldsm_x4(a4[mf], sb + panel_off(r, kb + la_kb));
            }
#pragma unroll
            for (int np = 0; np < 2; np++) {
                uint32_t n = (uint32_t)(nw * 32 + np * 16) + lb_r;
                uint32_t b4[4];
                ldsm_x4(b4, Bp + panel_off(n, kb + lb_kb));
#pragma unroll
                for (int mf = 0; mf < 2; mf++) {
                    MMA16816(c[mf][np * 2],     a4[mf], b4);
                    MMA16816(c[mf][np * 2 + 1], a4[mf], b4 + 2);
                }
            }
        }
    }
    __syncthreads();

    {
        const int l4 = lane >> 2;
        const int l2 = (lane & 3) * 2;
        const uint32_t hb = (uint32_t)(nw >> 1) * 8192u;
#pragma unroll
        for (int nf = 0; nf < 4; nf++) {
            int col = nw * 32 + nf * 8 + l2;
            float b0 = __ldg(nb1 + col), b1 = __ldg(nb1 + col + 1);
            uint32_t kk = (uint32_t)((nw & 1) * 32 + nf * 8 + l2);
#pragma unroll
            for (int mf = 0; mf < 2; mf++) {
                uint32_t m = (uint32_t)(mw * 32 + mf * 16 + l4);
                float x0 = silu_f(c[mf][nf][0] + b0);
                float x1 = silu_f(c[mf][nf][1] + b1);
                float x2 = silu_f(c[mf][nf][2] + b0);
                float x3 = silu_f(c[mf][nf][3] + b1);
                *(uint32_t*)(dsm + hb + panel_off(m, kk))     = f16x2(x0, x1);
                *(uint32_t*)(dsm + hb + panel_off(m + 8, kk)) = f16x2(x2, x3);
            }
        }
    }
    CP_WAIT(0);
    __syncthreads();

    float c2[2][4][4];
#pragma unroll
    for (int a = 0; a < 2; a++)
#pragma unroll
        for (int b = 0; b < 4; b++)
#pragma unroll
            for (int d = 0; d < 4; d++) c2[a][b][d] = 0.f;

#pragma unroll
    for (int p = 0; p < 2; p++) {
        const uint32_t Ap = sb + (uint32_t)p * 8192u;
        const uint32_t Bp = sb + 40960u + (uint32_t)p * 16384u;
#pragma unroll
        for (int ks = 0; ks < 4; ks++) {
            const uint32_t kb = ks * 16;
            uint32_t a4[2][4];
#pragma unroll
            for (int mf = 0; mf < 2; mf++) {
                uint32_t r = (uint32_t)(mw * 32 + mf * 16) + la_r;
                ldsm_x4(a4[mf], Ap + panel_off(r, kb + la_kb));
            }
#pragma unroll
            for (int np = 0; np < 2; np++) {
                uint32_t n = (uint32_t)(nw * 32 + np * 16) + lb_r;
                uint32_t b4[4];
                ldsm_x4(b4, Bp + panel_off(n, kb + lb_kb));
#pragma unroll
                for (int mf = 0; mf < 2; mf++) {
                    MMA16816(c2[mf][np * 2],     a4[mf], b4);
                    MMA16816(c2[mf][np * 2 + 1], a4[mf], b4 + 2);
                }
            }
        }
    }

    {
        const int l4 = lane >> 2;
        const int l2 = (lane & 3) * 2;
        float b0[4], b1[4];
#pragma unroll
        for (int nf = 0; nf < 4; nf++) {
            int col = nw * 32 + nf * 8 + l2;
            b0[nf] = __ldg(nb2 + col);
            b1[nf] = __ldg(nb2 + col + 1);
        }
#pragma unroll
        for (int mf = 0; mf < 2; mf++) {
#pragma unroll
            for (int half = 0; half < 2; half++) {
                size_t row = (size_t)m0 + mw * 32 + mf * 16 + l4 + half * 8;
                if (row < N_NODES) {
                    float* orow = nodes_out + row * NODE_C;
#pragma unroll
                    for (int nf = 0; nf < 4; nf++) {
                        int col = nw * 32 + nf * 8 + l2;
                        float2 ov;
                        ov.x = c2[mf][nf][half * 2]     + b0[nf];
                        ov.y = c2[mf][nf][half * 2 + 1] + b1[nf];
                        *reinterpret_cast<float2*>(orow + col) = ov;
                    }
                }
            }
        }
    }
}

// ---------------------------------------------------------------------------
extern "C" void kernel_launch(void* const* d_in, const int* in_sizes, int n_in,
                              void* d_out, int out_size)
{
    const float* xn   = (const float*)d_in[0];
    const float* xe   = (const float*)d_in[1];
    const void*  eidx =               d_in[2];
    const float* eW1  = (const float*)d_in[3];
    const float* eb1  = (const float*)d_in[4];
    const float* eW2  = (const float*)d_in[5];
    const float* eb2  = (const float*)d_in[6];
    const float* nW1  = (const float*)d_in[7];
    const float* nb1  = (const float*)d_in[8];
    const float* nW2  = (const float*)d_in[9];
    const float* nb2  = (const float*)d_in[10];

    float* nodes_out = (float*)d_out;
    float* edges_out = (float*)d_out + (size_t)N_NODES * NODE_C;

    cudaFuncSetAttribute(precompute_P_kernel, cudaFuncAttributeMaxDynamicSharedMemorySize, PREP_P_SMEM);
    cudaFuncSetAttribute(edge_mma_kernel, cudaFuncAttributeMaxDynamicSharedMemorySize, EDGE_SMEM);
    cudaFuncSetAttribute(node_mma_kernel, cudaFuncAttributeMaxDynamicSharedMemorySize, NODE_SMEM);

    prep_kernel<<<9535, 256>>>(xn, eW1, eW2, nW1, nW2);
    precompute_P_kernel<<<(N_NODES + 127) / 128, 256, PREP_P_SMEM>>>();
    edge_mma_kernel<<<N_EDGES / 64, 256, EDGE_SMEM>>>(xe, eidx, eb1, eb2, edges_out);
    node_mma_kernel<<<(N_NODES + 63) / 64, 256, NODE_SMEM>>>(xn, nb1, nb2, nodes_out);
}

// round 17
// speedup vs baseline: 1.4682x; 1.0835x over previous
#include <cuda_runtime.h>
#include <cuda_fp16.h>
#include <cstdint>

#define N_NODES 50000
#define N_EDGES 800000
#define NODE_C  128
#define EDGE_C  64

// ---------------------------------------------------------------------------
// Device scratch (no cudaMalloc allowed)
// ---------------------------------------------------------------------------
__device__ float g_aggr[(size_t)N_NODES * EDGE_C];
// P (fp16): [n][0:128]=xn@eW1[0:128], [n][128:256]=xn@eW1[128:256]
__device__ __align__(16) __half g_P_h[(size_t)N_NODES * 256];
__device__ __align__(16) __half g_xn_h[(size_t)N_NODES * NODE_C];
__device__ __align__(16) __half g_eW1t[128 * 320];
__device__ __align__(16) __half g_eW2t[64 * 128];
__device__ __align__(16) __half g_nW1t[128 * 192];
__device__ __align__(16) __half g_nW2t[128 * 128];

// ---------------------------------------------------------------------------
// Helpers
// ---------------------------------------------------------------------------
__device__ __forceinline__ uint32_t smem_u32(const void* p) {
    uint32_t a;
    asm("{ .reg .u64 t; cvta.to.shared.u64 t, %1; cvt.u32.u64 %0, t; }"
        : "=r"(a) : "l"(p));
    return a;
}

// Panels: [rows][64] fp16, 128-byte rows, XOR-swizzled 16B blocks.
__device__ __forceinline__ uint32_t panel_off(uint32_t r, uint32_t k) {
    return r * 128u + ((((k >> 3) ^ (r & 7u)) << 4) | ((k & 7u) << 1));
}

__device__ __forceinline__ void ldsm_x4(uint32_t* d, uint32_t a) {
    asm volatile("ldmatrix.sync.aligned.m8n8.x4.shared.b16 {%0,%1,%2,%3}, [%4];"
                 : "=r"(d[0]), "=r"(d[1]), "=r"(d[2]), "=r"(d[3]) : "r"(a));
}

#define MMA16816(c, a, b) \
    asm volatile("mma.sync.aligned.m16n8k16.row.col.f32.f16.f16.f32 " \
        "{%0,%1,%2,%3},{%4,%5,%6,%7},{%8,%9},{%0,%1,%2,%3};" \
        : "+f"((c)[0]), "+f"((c)[1]), "+f"((c)[2]), "+f"((c)[3]) \
        : "r"((a)[0]), "r"((a)[1]), "r"((a)[2]), "r"((a)[3]), \
          "r"((b)[0]), "r"((b)[1]))

__device__ __forceinline__ void cp16(uint32_t dst, const void* src) {
    asm volatile("cp.async.cg.shared.global [%0], [%1], 16;"
                 :: "r"(dst), "l"(src) : "memory");
}
#define CP_COMMIT() asm volatile("cp.async.commit_group;" ::: "memory")
#define CP_WAIT(n)  asm volatile("cp.async.wait_group %0;" :: "n"(n) : "memory")

__device__ __forceinline__ void red2(float* p, float2 v) {
    asm volatile("red.global.add.v2.f32 [%0], {%1,%2};"
                 :: "l"(p), "f"(v.x), "f"(v.y) : "memory");
}

__device__ __forceinline__ uint32_t f16x2(float lo, float hi) {
    uint32_t r;
    asm("cvt.rn.f16x2.f32 %0, %1, %2;" : "=r"(r) : "f"(hi), "f"(lo));
    return r;
}
__device__ __forceinline__ float silu_f(float x) {
    return x / (1.0f + __expf(-x));
}
__device__ __forceinline__ uint4 pack8(float4 v0, float4 v1) {
    uint4 r;
    r.x = f16x2(v0.x, v0.y);
    r.y = f16x2(v0.z, v0.w);
    r.z = f16x2(v1.x, v1.y);
    r.w = f16x2(v1.z, v1.w);
    return r;
}

// ---------------------------------------------------------------------------
// Fused prep (R13 verbatim)
// ---------------------------------------------------------------------------
__global__ void prep_kernel(const float* __restrict__ xn,
                            const float* __restrict__ eW1,
                            const float* __restrict__ eW2,
                            const float* __restrict__ nW1,
                            const float* __restrict__ nW2) {
    int b = blockIdx.x;
    if (b < 3125) {
        size_t i = (size_t)b * 256 + threadIdx.x;
        if (i < (size_t)N_NODES * EDGE_C / 4)
            reinterpret_cast<float4*>(g_aggr)[i] = make_float4(0.f, 0.f, 0.f, 0.f);
    } else if (b < 9375) {
        size_t i = (size_t)(b - 3125) * 256 + threadIdx.x;
        if (i < (size_t)N_NODES * NODE_C / 4) {
            float4 v = reinterpret_cast<const float4*>(xn)[i];
            uint2 h;
            h.x = f16x2(v.x, v.y);
            h.y = f16x2(v.z, v.w);
            reinterpret_cast<uint2*>(g_xn_h)[i] = h;
        }
    } else {
        int i = (b - 9375) * 256 + threadIdx.x;
        if (i < 128 * 320) {
            int n = i / 320, k = i % 320;
            g_eW1t[i] = __float2half_rn(eW1[(size_t)k * 128 + n]);
        }
        if (i < 64 * 128) {
            int n = i / 128, k = i % 128;
            g_eW2t[i] = __float2half_rn(eW2[(size_t)k * 64 + n]);
        }
        if (i < 128 * 192) {
            int n = i / 192, k = i % 192;
            g_nW1t[i] = __float2half_rn(nW1[(size_t)k * 128 + n]);
        }
        if (i < 128 * 128) {
            int n = i / 128, k = i % 128;
            g_nW2t[i] = __float2half_rn(nW2[(size_t)k * 128 + n]);
        }
    }
}

// ---------------------------------------------------------------------------
// Precompute P (fp16 output): [50k,128] @ [128,256]  (R15 verbatim)
// ---------------------------------------------------------------------------
#define PREP_P_SMEM 98304

__global__ __launch_bounds__(256, 2)
void precompute_P_kernel() {
    extern __shared__ __align__(1024) char dsm[];
    const int tid  = threadIdx.x;
    const int wid  = tid >> 5;
    const int lane = tid & 31;
    const int mw   = wid & 3;
    const int nw   = wid >> 2;
    const int m0   = blockIdx.x * 128;

    const uint32_t sb = smem_u32(dsm);
    const uint32_t la_r  = lane & 15;
    const uint32_t la_kb = (lane >> 4) << 3;
    const uint32_t lb_r  = (lane & 7) | ((lane >> 4) << 3);
    const uint32_t lb_kb = ((lane >> 3) & 1) << 3;

    {
        const int r = tid >> 1;
        const int half = tid & 1;
        const size_t node = (size_t)m0 + r;
        if (node < N_NODES) {
            const __half* a = g_xn_h + node * NODE_C + half * 64;
#pragma unroll
            for (int j = 0; j < 8; j++)
                cp16(sb + (uint32_t)(half * 16384) + panel_off((uint32_t)r, (uint32_t)(j * 8)), a + j * 8);
        } else {
            uint4 z = {0, 0, 0, 0};
#pragma unroll
            for (int j = 0; j < 8; j++)
                *(uint4*)(dsm + half * 16384 + panel_off((uint32_t)r, (uint32_t)(j * 8))) = z;
        }
    }
    {
        const int n = tid >> 1;
        const int hb = tid & 1;
#pragma unroll
        for (int kc2 = 0; kc2 < 2; kc2++) {
            int kc = hb * 2 + kc2;
            const __half* s = g_eW1t + (size_t)n * 320 + kc * 64;
#pragma unroll
            for (int j = 0; j < 8; j++)
                cp16(sb + 32768u + (uint32_t)(kc * 16384) + panel_off((uint32_t)n, (uint32_t)(j * 8)), s + j * 8);
        }
    }
    CP_COMMIT();
    CP_WAIT(0);
    __syncthreads();

#pragma unroll 1
    for (int o = 0; o < 2; o++) {
        float c[2][8][4];
#pragma unroll
        for (int a = 0; a < 2; a++)
#pragma unroll
            for (int b = 0; b < 8; b++)
#pragma unroll
                for (int d = 0; d < 4; d++) c[a][b][d] = 0.f;

#pragma unroll
        for (int p = 0; p < 2; p++) {
            const uint32_t Ap = sb + (uint32_t)p * 16384u;
            const uint32_t Bp = sb + 32768u + (uint32_t)(o * 2 + p) * 16384u;
#pragma unroll
            for (int ks = 0; ks < 4; ks++) {
                const uint32_t kb = ks * 16;
                uint32_t a4[2][4];
#pragma unroll
                for (int mf = 0; mf < 2; mf++) {
                    uint32_t r = (uint32_t)(mw * 32 + mf * 16) + la_r;
                    ldsm_x4(a4[mf], Ap + panel_off(r, kb + la_kb));
                }
#pragma unroll
                for (int np = 0; np < 4; np++) {
                    uint32_t n = (uint32_t)(nw * 64 + np * 16) + lb_r;
                    uint32_t b4[4];
                    ldsm_x4(b4, Bp + panel_off(n, kb + lb_kb));
#pragma unroll
                    for (int mf = 0; mf < 2; mf++) {
                        MMA16816(c[mf][np * 2],     a4[mf], b4);
                        MMA16816(c[mf][np * 2 + 1], a4[mf], b4 + 2);
                    }
                }
            }
        }
        const int l4 = lane >> 2;
        const int l2 = (lane & 3) * 2;
#pragma unroll
        for (int mf = 0; mf < 2; mf++) {
#pragma unroll
            for (int half = 0; half < 2; half++) {
                size_t node = (size_t)m0 + mw * 32 + mf * 16 + l4 + half * 8;
                if (node < N_NODES) {
                    __half* prow = g_P_h + node * 256 + o * 128;
#pragma unroll
                    for (int nf = 0; nf < 8; nf++) {
                        int col = nw * 64 + nf * 8 + l2;
                        *(uint32_t*)(prow + col) = f16x2(c[mf][nf][half * 2], c[mf][nf][half * 2 + 1]);
                    }
                }
            }
        }
    }
}

// ---------------------------------------------------------------------------
// Edge kernel: 4 tiles of 64 edges per CTA (256 edges), 256 threads, 2 CTAs/SM.
// Weights loaded once; P(t+1) prefetched during GEMM2/epilogue2 of tile t.
// SMEM 90KB:
//   XE  @0      (8K)   xe fp16 panel [64][64]
//   H   @8K     (16K)  h panels p0@8K p1@16K
//   B1  @24K    (16K)  eW1t k256..320 [128][64]
//   B2  @40K    (16K)  eW2t p0@40K p1@48K
//   PS  @56K    (17K)  P[snd] stage [64 rows][272B stride]
//   PR  @73K    (17K)  P[rcv] stage
// ---------------------------------------------------------------------------
#define XE_OFF 0u
#define H_OFF  8192u
#define B1_OFF 24576u
#define B2_OFF 40960u
#define PS_OFF 57344u
#define PR_OFF 74752u
#define EDGE_SMEM 92160
#define NODE_SMEM 73728
#define TILES_PER_CTA 4

__global__ __launch_bounds__(256, 2)
void edge_mma_kernel(const float* __restrict__ xe,
                     const void*  __restrict__ eidx,
                     const float* __restrict__ eb1,
                     const float* __restrict__ eb2,
                     float* __restrict__ edges_out)
{
    extern __shared__ __align__(1024) char dsm[];
    __shared__ int s_snd[256], s_rcv[256];

    const int tid  = threadIdx.x;
    const int wid  = tid >> 5;
    const int lane = tid & 31;
    const int mw   = wid & 1;      // 2 M strips (32 rows)
    const int nw   = wid >> 1;     // 4 N strips
    const int ebase = blockIdx.x * 256;   // first edge of this CTA

    const uint32_t sb = smem_u32(dsm);
    const uint32_t la_r  = lane & 15;
    const uint32_t la_kb = (lane >> 4) << 3;
    const uint32_t lb_r  = (lane & 7) | ((lane >> 4) << 3);
    const uint32_t lb_kb = ((lane >> 3) & 1) << 3;

    // all 256 edge indices up front
    {
        const unsigned* w = reinterpret_cast<const unsigned*>(eidx);
        const bool is64 = ((w[1] | w[3] | w[5] | w[7] | w[9] | w[11] | w[13] | w[15]) == 0u);
        size_t e = (size_t)ebase + tid;
        if (is64) {
            const long long* p = reinterpret_cast<const long long*>(eidx);
            s_snd[tid] = (int)p[e];
            s_rcv[tid] = (int)p[(size_t)N_EDGES + e];
        } else {
            const int* p = reinterpret_cast<const int*>(eidx);
            s_snd[tid] = p[e];
            s_rcv[tid] = p[(size_t)N_EDGES + e];
        }
    }
    __syncthreads();

    const int prow = tid >> 2;     // 0..63 (P gather row)
    const int pq   = tid & 3;      // 64B quarter
    const uint32_t pbase = (uint32_t)(prow * 272 + pq * 64);

    // prologue group: B1 + B2 + P(tile 0)
    {
        const int n = tid >> 1;
        const int bq = tid & 1;
        const __half* s = g_eW1t + (size_t)n * 320 + 256 + bq * 32;
#pragma unroll
        for (int j = 0; j < 4; j++)
            cp16(sb + B1_OFF + panel_off((uint32_t)n, (uint32_t)(bq * 32 + j * 8)), s + j * 8);

        const int n2 = tid >> 2;
        const int q2 = tid & 3;
        const __half* s2 = g_eW2t + (size_t)n2 * 128;
#pragma unroll
        for (int j = 0; j < 4; j++) {
            int seg = q2 * 4 + j;
            uint32_t p = (uint32_t)(seg >> 3);
            cp16(sb + B2_OFF + p * 8192u + panel_off((uint32_t)n2, (uint32_t)((seg & 7) * 8)), s2 + seg * 8);
        }

        const __half* ps = g_P_h + (size_t)s_snd[prow] * 256 + pq * 32;
        const __half* pr = g_P_h + (size_t)s_rcv[prow] * 256 + 128 + pq * 32;
#pragma unroll
        for (int j = 0; j < 4; j++) {
            cp16(sb + PS_OFF + pbase + j * 16, ps + j * 8);
            cp16(sb + PR_OFF + pbase + j * 16, pr + j * 8);
        }
        CP_COMMIT();
    }

#pragma unroll 1
    for (int t = 0; t < TILES_PER_CTA; t++) {
        __syncthreads();   // tile boundary: prev GEMM2 done with h; xe free
        const int e0 = ebase + t * 64;

        // xe(t) -> fp16 panel
        {
            const int row = tid >> 2;
            const int q   = tid & 3;
            const float4* rp = reinterpret_cast<const float4*>(xe + (size_t)(e0 + row) * EDGE_C) + q * 4;
            float4 v0 = rp[0], v1 = rp[1], v2 = rp[2], v3 = rp[3];
            *(uint4*)(dsm + XE_OFF + panel_off((uint32_t)row, (uint32_t)(q * 16)))     = pack8(v0, v1);
            *(uint4*)(dsm + XE_OFF + panel_off((uint32_t)row, (uint32_t)(q * 16 + 8))) = pack8(v2, v3);
        }
        CP_WAIT(0);        // P(t) (and weights at t=0) arrived
        __syncthreads();

        // ---------------- GEMM1': xe[64,64] @ B1^T -> frag [64,128] ----------------
        float c1[2][4][4];
#pragma unroll
        for (int a = 0; a < 2; a++)
#pragma unroll
            for (int b = 0; b < 4; b++)
#pragma unroll
                for (int d = 0; d < 4; d++) c1[a][b][d] = 0.f;

#pragma unroll
        for (int ks = 0; ks < 4; ks++) {
            const uint32_t kb = ks * 16;
            uint32_t a4[2][4];
#pragma unroll
            for (int mf = 0; mf < 2; mf++) {
                uint32_t r = (uint32_t)(mw * 32 + mf * 16) + la_r;
                ldsm_x4(a4[mf], sb + XE_OFF + panel_off(r, kb + la_kb));
            }
#pragma unroll
            for (int np = 0; np < 2; np++) {
                uint32_t n = (uint32_t)(nw * 32 + np * 16) + lb_r;
                uint32_t b4[4];
                ldsm_x4(b4, sb + B1_OFF + panel_off(n, kb + lb_kb));
#pragma unroll
                for (int mf = 0; mf < 2; mf++) {
                    MMA16816(c1[mf][np * 2],     a4[mf], b4);
                    MMA16816(c1[mf][np * 2 + 1], a4[mf], b4 + 2);
                }
            }
        }

        // ---- Epilogue1 (fragment layout): c1 + Ps + Pr + bias -> SiLU -> h ----
        {
            const int l4 = lane >> 2;
            const int l2 = (lane & 3) * 2;
#pragma unroll
            for (int nf = 0; nf < 4; nf++) {
                int col = nw * 32 + nf * 8 + l2;
                float b0 = __ldg(eb1 + col), b1 = __ldg(eb1 + col + 1);
                const uint32_t hpan = H_OFF + (uint32_t)(col >> 6) * 8192u;
                const uint32_t kk = (uint32_t)(col & 63);
#pragma unroll
                for (int mf = 0; mf < 2; mf++) {
#pragma unroll
                    for (int half = 0; half < 2; half++) {
                        uint32_t row = (uint32_t)(mw * 32 + mf * 16 + l4 + half * 8);
                        __half2 hs = *(__half2*)(dsm + PS_OFF + row * 272 + col * 2);
                        __half2 hr = *(__half2*)(dsm + PR_OFF + row * 272 + col * 2);
                        float x0 = silu_f(c1[mf][nf][half * 2]     + __low2float(hs)  + __low2float(hr)  + b0);
                        float x1 = silu_f(c1[mf][nf][half * 2 + 1] + __high2float(hs) + __high2float(hr) + b1);
                        *(uint32_t*)(dsm + hpan + panel_off(row, kk)) = f16x2(x0, x1);
                    }
                }
            }
        }
        __syncthreads();   // Ps/Pr consumed; h complete

        // prefetch P(t+1) — hides under GEMM2 + epilogue2
        if (t + 1 < TILES_PER_CTA) {
            const int nt = (t + 1) * 64 + prow;
            const __half* ps = g_P_h + (size_t)s_snd[nt] * 256 + pq * 32;
            const __half* pr = g_P_h + (size_t)s_rcv[nt] * 256 + 128 + pq * 32;
#pragma unroll
            for (int j = 0; j < 4; j++) {
                cp16(sb + PS_OFF + pbase + j * 16, ps + j * 8);
                cp16(sb + PR_OFF + pbase + j * 16, pr + j * 8);
            }
            CP_COMMIT();
        }

        // ---------------- GEMM2: h[64,128] @ eW2t^T -> [64,64] ----------------
        float c2[2][2][4];
#pragma unroll
        for (int a = 0; a < 2; a++)
#pragma unroll
            for (int b = 0; b < 2; b++)
#pragma unroll
                for (int d = 0; d < 4; d++) c2[a][b][d] = 0.f;

#pragma unroll
        for (int p = 0; p < 2; p++) {
            const uint32_t Ap = sb + H_OFF + (uint32_t)p * 8192u;
            const uint32_t Bp = sb + B2_OFF + (uint32_t)p * 8192u;
#pragma unroll
            for (int ks = 0; ks < 4; ks++) {
                const uint32_t kb = ks * 16;
                uint32_t a4[2][4];
#pragma unroll
                for (int mf = 0; mf < 2; mf++) {
                    uint32_t r = (uint32_t)(mw * 32 + mf * 16) + la_r;
                    ldsm_x4(a4[mf], Ap + panel_off(r, kb + la_kb));
                }
                uint32_t n = (uint32_t)(nw * 16) + lb_r;
                uint32_t b4[4];
                ldsm_x4(b4, Bp + panel_off(n, kb + lb_kb));
#pragma unroll
                for (int mf = 0; mf < 2; mf++) {
                    MMA16816(c2[mf][0], a4[mf], b4);
                    MMA16816(c2[mf][1], a4[mf], b4 + 2);
                }
            }
        }

        // ---------------- Epilogue2: SiLU, store, red.v2 scatter-add ----------------
        {
            const int l4 = lane >> 2;
            const int l2 = (lane & 3) * 2;
            float b0[2], b1[2];
#pragma unroll
            for (int nf = 0; nf < 2; nf++) {
                int col = nw * 16 + nf * 8 + l2;
                b0[nf] = __ldg(eb2 + col);
                b1[nf] = __ldg(eb2 + col + 1);
            }
#pragma unroll
            for (int mf = 0; mf < 2; mf++) {
#pragma unroll
                for (int half = 0; half < 2; half++) {
                    int m = mw * 32 + mf * 16 + l4 + half * 8;
                    int rcv = s_rcv[t * 64 + m];
                    float* orow = edges_out + (size_t)(e0 + m) * EDGE_C;
                    float* arow = g_aggr + (size_t)rcv * EDGE_C;
#pragma unroll
                    for (int nf = 0; nf < 2; nf++) {
                        int col = nw * 16 + nf * 8 + l2;
                        float o0 = silu_f(c2[mf][nf][half * 2]     + b0[nf]);
                        float o1 = silu_f(c2[mf][nf][half * 2 + 1] + b1[nf]);
                        float2 ov = {o0, o1};
                        *reinterpret_cast<float2*>(orow + col) = ov;
                        red2(arow + col, ov);
                    }
                }
            }
        }
    }
}

// ---------------------------------------------------------------------------
// Node kernel: 64 nodes / CTA, 256 threads, 2 CTAs/SM (R13 verbatim)
// ---------------------------------------------------------------------------
__global__ __launch_bounds__(256, 2)
void node_mma_kernel(const float* __restrict__ xn,
                     const float* __restrict__ nb1,
                     const float* __restrict__ nb2,
                     float* __restrict__ nodes_out)
{
    extern __shared__ __align__(1024) char dsm[];

    const int tid  = threadIdx.x;
    const int wid  = tid >> 5;
    const int lane = tid & 31;
    const int mw   = wid & 1;
    const int nw   = wid >> 1;
    const int m0   = blockIdx.x * 64;

    const uint32_t sb = smem_u32(dsm);
    const uint32_t la_r  = lane & 15;
    const uint32_t la_kb = (lane >> 4) << 3;
    const uint32_t lb_r  = (lane & 7) | ((lane >> 4) << 3);
    const uint32_t lb_kb = ((lane >> 3) & 1) << 3;

    const int gm = tid >> 2;
    const int gq = tid & 3;
    const int bn = tid >> 1;
    const int bq = tid & 1;
    const size_t grow = (size_t)m0 + gm;
    const bool gvalid = grow < N_NODES;

    {
        const __half* s = g_nW1t + (size_t)bn * 192 + bq * 32;
#pragma unroll
        for (int j = 0; j < 4; j++) {
            uint32_t off = panel_off((uint32_t)bn, (uint32_t)(bq * 32 + j * 8));
            cp16(sb + 8192u + off, s + j * 8);
        }
        CP_COMMIT();
    }
    float4 av[4];
    {
        const float4* rp = reinterpret_cast<const float4*>(xn + grow * NODE_C) + gq * 4;
#pragma unroll
        for (int i = 0; i < 4; i++)
            av[i] = gvalid ? rp[i] : make_float4(0.f, 0.f, 0.f, 0.f);
    }

    float c[2][4][4];
#pragma unroll
    for (int a = 0; a < 2; a++)
#pragma unroll
        for (int b = 0; b < 4; b++)
#pragma unroll
            for (int d = 0; d < 4; d++) c[a][b][d] = 0.f;

#pragma unroll 1
    for (int ch = 0; ch < 3; ch++) {
        __syncthreads();
#pragma unroll
        for (int i = 0; i < 2; i++) {
            uint32_t off = panel_off((uint32_t)gm, (uint32_t)(gq * 16 + i * 8));
            *(uint4*)(dsm + off) = pack8(av[2 * i], av[2 * i + 1]);
        }
        if (ch < 2) {
            const int nc = ch + 1;
            uint32_t dst = 8192u + (uint32_t)((nc & 1) * 16384);
            const __half* s = g_nW1t + (size_t)bn * 192 + nc * 64 + bq * 32;
#pragma unroll
            for (int j = 0; j < 4; j++) {
                uint32_t off = panel_off((uint32_t)bn, (uint32_t)(bq * 32 + j * 8));
                cp16(sb + dst + off, s + j * 8);
            }
            CP_COMMIT();
            const float* rowp = (nc < 2) ? xn + grow * NODE_C + nc * 64
                                         : g_aggr + grow * EDGE_C;
            const float4* rp = reinterpret_cast<const float4*>(rowp) + gq * 4;
#pragma unroll
            for (int i = 0; i < 4; i++)
                av[i] = gvalid ? rp[i] : make_float4(0.f, 0.f, 0.f, 0.f);
        } else {
            const __half* s = g_nW2t + (size_t)bn * 128;
#pragma unroll
            for (int j = 0; j < 8; j++) {
                int seg = bq * 8 + j;
                uint32_t p = (uint32_t)(seg >> 3);
                uint32_t off = p * 16384u + panel_off((uint32_t)bn, (uint32_t)((seg & 7) * 8));
                cp16(sb + 40960u + off, s + seg * 8);
            }
            CP_COMMIT();
        }
        CP_WAIT(1);
        __syncthreads();

        const uint32_t Bp = sb + 8192u + (uint32_t)((ch & 1) * 16384);
#pragma unroll
        for (int ks = 0; ks < 4; ks++) {
            const uint32_t kb = ks * 16;
            uint32_t a4[2][4];
#pragma unroll
            for (int mf = 0; mf < 2; mf++) {
                uint32_t r = (uint32_t)(mw * 32 + mf * 16) + la_r;
                ldsm_x4(a4[mf], sb + panel_off(r, kb + la_kb));
            }
#pragma unroll
            for (int np = 0; np < 2; np++) {
                uint32_t n = (uint32_t)(nw * 32 + np * 16) + lb_r;
                uint32_t b4[4];
                ldsm_x4(b4, Bp + panel_off(n, kb + lb_kb));
#pragma unroll
                for (int mf = 0; mf < 2; mf++) {
                    MMA16816(c[mf][np * 2],     a4[mf], b4);
                    MMA16816(c[mf][np * 2 + 1], a4[mf], b4 + 2);
                }
            }
        }
    }
    __syncthreads();

    {
        const int l4 = lane >> 2;
        const int l2 = (lane & 3) * 2;
        const uint32_t hb = (uint32_t)(nw >> 1) * 8192u;
#pragma unroll
        for (int nf = 0; nf < 4; nf++) {
            int col = nw * 32 + nf * 8 + l2;
            float b0 = __ldg(nb1 + col), b1 = __ldg(nb1 + col + 1);
            uint32_t kk = (uint32_t)((nw & 1) * 32 + nf * 8 + l2);
#pragma unroll
            for (int mf = 0; mf < 2; mf++) {
                uint32_t m = (uint32_t)(mw * 32 + mf * 16 + l4);
                float x0 = silu_f(c[mf][nf][0] + b0);
                float x1 = silu_f(c[mf][nf][1] + b1);
                float x2 = silu_f(c[mf][nf][2] + b0);
                float x3 = silu_f(c[mf][nf][3] + b1);
                *(uint32_t*)(dsm + hb + panel_off(m, kk))     = f16x2(x0, x1);
                *(uint32_t*)(dsm + hb + panel_off(m + 8, kk)) = f16x2(x2, x3);
            }
        }
    }
    CP_WAIT(0);
    __syncthreads();

    float c2[2][4][4];
#pragma unroll
    for (int a = 0; a < 2; a++)
#pragma unroll
        for (int b = 0; b < 4; b++)
#pragma unroll
            for (int d = 0; d < 4; d++) c2[a][b][d] = 0.f;

#pragma unroll
    for (int p = 0; p < 2; p++) {
        const uint32_t Ap = sb + (uint32_t)p * 8192u;
        const uint32_t Bp = sb + 40960u + (uint32_t)p * 16384u;
#pragma unroll
        for (int ks = 0; ks < 4; ks++) {
            const uint32_t kb = ks * 16;
            uint32_t a4[2][4];
#pragma unroll
            for (int mf = 0; mf < 2; mf++) {
                uint32_t r = (uint32_t)(mw * 32 + mf * 16) + la_r;
                ldsm_x4(a4[mf], Ap + panel_off(r, kb + la_kb));
            }
#pragma unroll
            for (int np = 0; np < 2; np++) {
                uint32_t n = (uint32_t)(nw * 32 + np * 16) + lb_r;
                uint32_t b4[4];
                ldsm_x4(b4, Bp + panel_off(n, kb + lb_kb));
#pragma unroll
                for (int mf = 0; mf < 2; mf++) {
                    MMA16816(c2[mf][np * 2],     a4[mf], b4);
                    MMA16816(c2[mf][np * 2 + 1], a4[mf], b4 + 2);
                }
            }
        }
    }

    {
        const int l4 = lane >> 2;
        const int l2 = (lane & 3) * 2;
        float b0[4], b1[4];
#pragma unroll
        for (int nf = 0; nf < 4; nf++) {
            int col = nw * 32 + nf * 8 + l2;
            b0[nf] = __ldg(nb2 + col);
            b1[nf] = __ldg(nb2 + col + 1);
        }
#pragma unroll
        for (int mf = 0; mf < 2; mf++) {
#pragma unroll
            for (int half = 0; half < 2; half++) {
                size_t row = (size_t)m0 + mw * 32 + mf * 16 + l4 + half * 8;
                if (row < N_NODES) {
                    float* orow = nodes_out + row * NODE_C;
#pragma unroll
                    for (int nf = 0; nf < 4; nf++) {
                        int col = nw * 32 + nf * 8 + l2;
                        float2 ov;
                        ov.x = c2[mf][nf][half * 2]     + b0[nf];
                        ov.y = c2[mf][nf][half * 2 + 1] + b1[nf];
                        *reinterpret_cast<float2*>(orow + col) = ov;
                    }
                }
            }
        }
    }
}

// ---------------------------------------------------------------------------
extern "C" void kernel_launch(void* const* d_in, const int* in_sizes, int n_in,
                              void* d_out, int out_size)
{
    const float* xn   = (const float*)d_in[0];
    const float* xe   = (const float*)d_in[1];
    const void*  eidx =               d_in[2];
    const float* eW1  = (const float*)d_in[3];
    const float* eb1  = (const float*)d_in[4];
    const float* eW2  = (const float*)d_in[5];
    const float* eb2  = (const float*)d_in[6];
    const float* nW1  = (const float*)d_in[7];
    const float* nb1  = (const float*)d_in[8];
    const float* nW2  = (const float*)d_in[9];
    const float* nb2  = (const float*)d_in[10];

    float* nodes_out = (float*)d_out;
    float* edges_out = (float*)d_out + (size_t)N_NODES * NODE_C;

    cudaFuncSetAttribute(precompute_P_kernel, cudaFuncAttributeMaxDynamicSharedMemorySize, PREP_P_SMEM);
    cudaFuncSetAttribute(edge_mma_kernel, cudaFuncAttributeMaxDynamicSharedMemorySize, EDGE_SMEM);
    cudaFuncSetAttribute(node_mma_kernel, cudaFuncAttributeMaxDynamicSharedMemorySize, NODE_SMEM);

    prep_kernel<<<9535, 256>>>(xn, eW1, eW2, nW1, nW2);
    precompute_P_kernel<<<(N_NODES + 127) / 128, 256, PREP_P_SMEM>>>();
    edge_mma_kernel<<<N_EDGES / (64 * TILES_PER_CTA), 256, EDGE_SMEM>>>(xe, eidx, eb1, eb2, edges_out);
    node_mma_kernel<<<(N_NODES + 63) / 64, 256, NODE_SMEM>>>(xn, nb1, nb2, nodes_out);
}